// round 1
// baseline (speedup 1.0000x reference)
#include <cuda_runtime.h>
#include <cuda_bf16.h>
#include <math.h>

#define BB 2
#define LLEN 2048
#define DDIM 1024
#define NHEAD 16
#define DHEAD 64

// ---------------- scratch (device globals; no allocations allowed) ----------------
__device__ float g_q[BB*LLEN*DDIM];
__device__ float g_k[BB*LLEN*DDIM];
__device__ float g_v[BB*LLEN*DDIM];
__device__ float g_q2[BB*LLEN*DDIM];
__device__ float g_k2[BB*LLEN*DDIM];
__device__ float g_ctx[BB*LLEN*DDIM];
__device__ float g_hid[BB*LLEN*DDIM];
__device__ float g_Pq[BB*DDIM*DDIM];
__device__ float g_Pk[BB*DDIM*DDIM];
__device__ float g_scq[BB*DDIM];
__device__ float g_sck[BB*DDIM];
__device__ float g_partq[BB*16*DDIM];
__device__ float g_partk[BB*16*DDIM];
__device__ float g_bsq[BB*DDIM];
__device__ float g_bsk[BB*DDIM];

// ---------------- GEMM: C[M,N] = A[M,K] @ Bt[N,K]^T (+bias) ----------------
// 64x64 tile, BK=16, 256 threads, 4x4 microtile.
__global__ void gemm_tn(const float* __restrict__ A, const float* __restrict__ Bt,
                        const float* __restrict__ bias, float* __restrict__ C,
                        int M, int N, int K)
{
    __shared__ float As[16][65];
    __shared__ float Bs[16][65];
    const int tid = threadIdx.x;
    const int tx  = tid & 15;
    const int ty  = tid >> 4;
    const int row0 = blockIdx.y * 64;
    const int col0 = blockIdx.x * 64;
    const int lr = tid >> 2;        // 0..63
    const int lc = (tid & 3) * 4;   // 0,4,8,12

    float acc[4][4];
#pragma unroll
    for (int i = 0; i < 4; i++)
#pragma unroll
        for (int j = 0; j < 4; j++) acc[i][j] = 0.f;

    for (int k0 = 0; k0 < K; k0 += 16) {
        float4 a4 = *(const float4*)&A[(size_t)(row0 + lr) * K + k0 + lc];
        float4 b4 = *(const float4*)&Bt[(size_t)(col0 + lr) * K + k0 + lc];
        As[lc+0][lr] = a4.x; As[lc+1][lr] = a4.y; As[lc+2][lr] = a4.z; As[lc+3][lr] = a4.w;
        Bs[lc+0][lr] = b4.x; Bs[lc+1][lr] = b4.y; Bs[lc+2][lr] = b4.z; Bs[lc+3][lr] = b4.w;
        __syncthreads();
#pragma unroll
        for (int k = 0; k < 16; k++) {
            float a[4], b[4];
#pragma unroll
            for (int i = 0; i < 4; i++) a[i] = As[k][ty*4 + i];
#pragma unroll
            for (int j = 0; j < 4; j++) b[j] = Bs[k][tx*4 + j];
#pragma unroll
            for (int i = 0; i < 4; i++)
#pragma unroll
                for (int j = 0; j < 4; j++) acc[i][j] += a[i] * b[j];
        }
        __syncthreads();
    }
#pragma unroll
    for (int i = 0; i < 4; i++) {
        int r = row0 + ty*4 + i;
#pragma unroll
        for (int j = 0; j < 4; j++) {
            int c = col0 + tx*4 + j;
            float v = acc[i][j];
            if (bias) v += bias[c];
            C[(size_t)r * N + c] = v;
        }
    }
}

// ---------------- column mean over L (two stage) ----------------
__global__ void colmean_part(const float* __restrict__ X, float* __restrict__ part)
{   // grid (B,16), block 1024
    int b = blockIdx.x, g = blockIdx.y, d = threadIdx.x;
    const float* Xb = X + (size_t)b * LLEN * DDIM;
    float s = 0.f;
    int l0 = g * (LLEN / 16);
    for (int t = 0; t < LLEN / 16; t++) s += Xb[(size_t)(l0 + t) * DDIM + d];
    part[((size_t)b * 16 + g) * DDIM + d] = s;
}

__global__ void colmean_fin(const float* __restrict__ part, float* __restrict__ sc)
{   // grid B, block 1024
    int b = blockIdx.x, d = threadIdx.x;
    float s = 0.f;
    for (int g = 0; g < 16; g++) s += part[((size_t)b * 16 + g) * DDIM + d];
    sc[b * DDIM + d] = s * (1.0f / LLEN);
}

// ---------------- Bsum_j = sum_k |s_j - s_k| ----------------
__global__ void bsum_kernel(const float* __restrict__ sc, float* __restrict__ bs)
{   // grid B, block 1024
    __shared__ float ss[1024];
    int b = blockIdx.x, j = threadIdx.x;
    float sj = sc[b * 1024 + j];
    ss[j] = sj;
    __syncthreads();
    float a = 0.f;
    for (int kk = 0; kk < 1024; kk++) a += fabsf(sj - ss[kk]);
    bs[b * 1024 + j] = a;
}

// ---------------- P[b,i,j] = softmax_j( s_j*(n-1-2i) - Bsum_j ) ----------------
__global__ void sortP_kernel(const float* __restrict__ sc, const float* __restrict__ bs,
                             float* __restrict__ P)
{   // grid (1024, B), block 256
    const int n = 1024;
    int i = blockIdx.x, b = blockIdx.y;
    int tid = threadIdx.x;
    const float* s  = sc + b * n;
    const float* Bv = bs + b * n;
    float scal = (float)(n - 1 - 2 * i);

    float v[4]; float mx = -1e30f;
#pragma unroll
    for (int t = 0; t < 4; t++) {
        int j = tid + t * 256;
        float x = s[j] * scal - Bv[j];
        v[t] = x; mx = fmaxf(mx, x);
    }
    __shared__ float sm[8];
    __shared__ float tot;
    for (int o = 16; o > 0; o >>= 1) mx = fmaxf(mx, __shfl_xor_sync(0xffffffffu, mx, o));
    if ((tid & 31) == 0) sm[tid >> 5] = mx;
    __syncthreads();
    if (tid == 0) { float t2 = sm[0]; for (int w = 1; w < 8; w++) t2 = fmaxf(t2, sm[w]); tot = t2; }
    __syncthreads();
    mx = tot;
    float sum = 0.f;
#pragma unroll
    for (int t = 0; t < 4; t++) { float e = expf(v[t] - mx); v[t] = e; sum += e; }
    __syncthreads();   // protect sm/tot reuse
    for (int o = 16; o > 0; o >>= 1) sum += __shfl_xor_sync(0xffffffffu, sum, o);
    if ((tid & 31) == 0) sm[tid >> 5] = sum;
    __syncthreads();
    if (tid == 0) { float t2 = 0.f; for (int w = 0; w < 8; w++) t2 += sm[w]; tot = t2; }
    __syncthreads();
    float inv = 1.0f / tot;
    float* Pr = P + ((size_t)b * n + i) * n;
#pragma unroll
    for (int t = 0; t < 4; t++) Pr[tid + t * 256] = v[t] * inv;
}

// ---------------- Euler pointwise (in-place, float2 pairs) ----------------
__global__ void euler_kernel(float* __restrict__ X, const float* __restrict__ delta,
                             const float* __restrict__ b_euler, const float* __restrict__ log_scale,
                             int add_b)
{   // one thread per (row, pair)
    int idx = blockIdx.x * blockDim.x + threadIdx.x;   // 0 .. B*L*512-1
    int i = idx & 511;
    float2 rp = ((float2*)X)[idx];
    float r = rp.x, p = rp.y;
    float lam = sqrtf(r * r + p * p + 1e-6f);
    float th = atan2f(p / lam, r / lam) * delta[i];
    if (add_b) th += b_euler[i];
    float ls = fminf(fmaxf(log_scale[i], -5.f), 5.f);
    lam = lam * expf(ls);
    ((float2*)X)[idx] = make_float2(lam * cosf(th), lam * sinf(th));
}

// ---------------- flash attention (fp32, online softmax) ----------------
// grid (L/64, B*H), block 256. Layout (B,L,D), head h occupies cols h*64..h*64+63.
__global__ void flash_kernel(const float* __restrict__ Q, const float* __restrict__ K,
                             const float* __restrict__ V, float* __restrict__ O)
{
    __shared__ float qs[64][65];
    __shared__ float ks[32][65];
    __shared__ float vs[32][65];
    __shared__ float ps[64][33];
    __shared__ float redA[64][4];
    __shared__ float redB[64][4];

    const int tid = threadIdx.x;
    const int r  = tid & 63;
    const int cg = tid >> 6;     // 0..3
    const int bh = blockIdx.y;
    const int b = bh >> 4, h = bh & 15;
    const int q0 = blockIdx.x * 64;
    const float* Qb = Q + (size_t)b * LLEN * DDIM + h * DHEAD;
    const float* Kb = K + (size_t)b * LLEN * DDIM + h * DHEAD;
    const float* Vb = V + (size_t)b * LLEN * DDIM + h * DHEAD;

    for (int e = tid; e < 64 * 64; e += 256) {
        int rr = e >> 6, dd = e & 63;
        qs[rr][dd] = Qb[(size_t)(q0 + rr) * DDIM + dd] * 0.125f;  // 1/sqrt(64)
    }

    float o[16];
#pragma unroll
    for (int i = 0; i < 16; i++) o[i] = 0.f;
    float m = -1e30f, l = 0.f;

    for (int k0 = 0; k0 < LLEN; k0 += 32) {
        __syncthreads();
        for (int e = tid; e < 32 * 64; e += 256) {
            int rr = e >> 6, dd = e & 63;
            ks[rr][dd] = Kb[(size_t)(k0 + rr) * DDIM + dd];
            vs[rr][dd] = Vb[(size_t)(k0 + rr) * DDIM + dd];
        }
        __syncthreads();

        float s[8];
#pragma unroll
        for (int j = 0; j < 8; j++) s[j] = 0.f;
        const int c0 = cg * 8;
#pragma unroll 8
        for (int d = 0; d < 64; d++) {
            float qv = qs[r][d];
#pragma unroll
            for (int j = 0; j < 8; j++) s[j] += qv * ks[c0 + j][d];
        }
        float pm = s[0];
#pragma unroll
        for (int j = 1; j < 8; j++) pm = fmaxf(pm, s[j]);
        redA[r][cg] = pm;
        __syncthreads();
        float mn = fmaxf(fmaxf(redA[r][0], redA[r][1]), fmaxf(redA[r][2], redA[r][3]));
        mn = fmaxf(m, mn);
        float psum = 0.f;
#pragma unroll
        for (int j = 0; j < 8; j++) {
            float pv = expf(s[j] - mn);
            ps[r][c0 + j] = pv;
            psum += pv;
        }
        redB[r][cg] = psum;
        __syncthreads();
        float ladd = redB[r][0] + redB[r][1] + redB[r][2] + redB[r][3];
        float scl = expf(m - mn);
        l = l * scl + ladd;
        m = mn;
        const int oc = cg * 16;
#pragma unroll
        for (int i = 0; i < 16; i++) o[i] *= scl;
#pragma unroll 4
        for (int j = 0; j < 32; j++) {
            float pv = ps[r][j];
#pragma unroll
            for (int i = 0; i < 16; i++) o[i] += pv * vs[j][oc + i];
        }
    }
    float inv = 1.0f / l;
    float* Ob = O + (size_t)b * LLEN * DDIM + h * DHEAD;
    const int oc = cg * 16;
#pragma unroll
    for (int i = 0; i < 16; i++)
        Ob[(size_t)(q0 + r) * DDIM + oc + i] = o[i] * inv;
}

// ---------------- residual + LayerNorm ----------------
__global__ void ln_kernel(const float* __restrict__ hid, const float* __restrict__ inp,
                          const float* __restrict__ gamma, const float* __restrict__ beta,
                          float* __restrict__ out)
{   // grid B*L, block 256
    size_t row = blockIdx.x;
    int tid = threadIdx.x;
    float x[4];
    float s = 0.f;
#pragma unroll
    for (int t = 0; t < 4; t++) {
        int d = tid + t * 256;
        x[t] = hid[row * DDIM + d] + inp[row * DDIM + d];
        s += x[t];
    }
    __shared__ float sm[8];
    __shared__ float tot;
    for (int o = 16; o > 0; o >>= 1) s += __shfl_xor_sync(0xffffffffu, s, o);
    if ((tid & 31) == 0) sm[tid >> 5] = s;
    __syncthreads();
    if (tid == 0) { float t2 = 0.f; for (int w = 0; w < 8; w++) t2 += sm[w]; tot = t2; }
    __syncthreads();
    float mu = tot * (1.0f / DDIM);
    float vsum = 0.f;
#pragma unroll
    for (int t = 0; t < 4; t++) { float dd = x[t] - mu; vsum += dd * dd; }
    __syncthreads();   // protect sm/tot reuse
    for (int o = 16; o > 0; o >>= 1) vsum += __shfl_xor_sync(0xffffffffu, vsum, o);
    if ((tid & 31) == 0) sm[tid >> 5] = vsum;
    __syncthreads();
    if (tid == 0) { float t2 = 0.f; for (int w = 0; w < 8; w++) t2 += sm[w]; tot = t2; }
    __syncthreads();
    float var = tot * (1.0f / DDIM);
    float inv = 1.0f / sqrtf(var + 1e-12f);
#pragma unroll
    for (int t = 0; t < 4; t++) {
        int d = tid + t * 256;
        out[row * DDIM + d] = (x[t] - mu) * inv * gamma[d] + beta[d];
    }
}

// ---------------- driver ----------------
extern "C" void kernel_launch(void* const* d_in, const int* in_sizes, int n_in,
                              void* d_out, int out_size)
{
    const float* X   = (const float*)d_in[0];
    const float* Wq  = (const float*)d_in[1];
    const float* bq  = (const float*)d_in[2];
    const float* Wk  = (const float*)d_in[3];
    const float* bk  = (const float*)d_in[4];
    const float* Wv  = (const float*)d_in[5];
    const float* bv  = (const float*)d_in[6];
    const float* Wd  = (const float*)d_in[7];
    const float* bd  = (const float*)d_in[8];
    const float* gamma     = (const float*)d_in[9];
    const float* beta      = (const float*)d_in[10];
    const float* delta     = (const float*)d_in[11];
    const float* b_euler   = (const float*)d_in[12];
    const float* log_scale = (const float*)d_in[13];
    float* out = (float*)d_out;

    float *q, *k, *v, *q2, *k2, *ctx, *hid, *Pq, *Pk, *scq, *sck, *pq, *pk, *bsq, *bsk;
    { void* p;
      cudaGetSymbolAddress(&p, g_q);    q   = (float*)p;
      cudaGetSymbolAddress(&p, g_k);    k   = (float*)p;
      cudaGetSymbolAddress(&p, g_v);    v   = (float*)p;
      cudaGetSymbolAddress(&p, g_q2);   q2  = (float*)p;
      cudaGetSymbolAddress(&p, g_k2);   k2  = (float*)p;
      cudaGetSymbolAddress(&p, g_ctx);  ctx = (float*)p;
      cudaGetSymbolAddress(&p, g_hid);  hid = (float*)p;
      cudaGetSymbolAddress(&p, g_Pq);   Pq  = (float*)p;
      cudaGetSymbolAddress(&p, g_Pk);   Pk  = (float*)p;
      cudaGetSymbolAddress(&p, g_scq);  scq = (float*)p;
      cudaGetSymbolAddress(&p, g_sck);  sck = (float*)p;
      cudaGetSymbolAddress(&p, g_partq); pq = (float*)p;
      cudaGetSymbolAddress(&p, g_partk); pk = (float*)p;
      cudaGetSymbolAddress(&p, g_bsq);  bsq = (float*)p;
      cudaGetSymbolAddress(&p, g_bsk);  bsk = (float*)p;
    }

    const int M = BB * LLEN;   // 4096

    // 1. projections
    gemm_tn<<<dim3(DDIM/64, M/64), 256>>>(X, Wq, bq, q, M, DDIM, DDIM);
    gemm_tn<<<dim3(DDIM/64, M/64), 256>>>(X, Wk, bk, k, M, DDIM, DDIM);
    gemm_tn<<<dim3(DDIM/64, M/64), 256>>>(X, Wv, bv, v, M, DDIM, DDIM);

    // 2. column means over L
    colmean_part<<<dim3(BB, 16), 1024>>>(q, pq);
    colmean_part<<<dim3(BB, 16), 1024>>>(k, pk);
    colmean_fin<<<BB, 1024>>>(pq, scq);
    colmean_fin<<<BB, 1024>>>(pk, sck);

    // 3. neural sort permutation matrices
    bsum_kernel<<<BB, 1024>>>(scq, bsq);
    bsum_kernel<<<BB, 1024>>>(sck, bsk);
    sortP_kernel<<<dim3(DDIM, BB), 256>>>(scq, bsq, Pq);
    sortP_kernel<<<dim3(DDIM, BB), 256>>>(sck, bsk, Pk);

    // 4. v_sorted = x @ P^T  (per batch)
    for (int b = 0; b < BB; b++) {
        gemm_tn<<<dim3(DDIM/64, LLEN/64), 256>>>(q + (size_t)b*LLEN*DDIM, Pq + (size_t)b*DDIM*DDIM,
                                                 nullptr, q2 + (size_t)b*LLEN*DDIM, LLEN, DDIM, DDIM);
        gemm_tn<<<dim3(DDIM/64, LLEN/64), 256>>>(k + (size_t)b*LLEN*DDIM, Pk + (size_t)b*DDIM*DDIM,
                                                 nullptr, k2 + (size_t)b*LLEN*DDIM, LLEN, DDIM, DDIM);
    }

    // 5. euler pointwise (in place)
    euler_kernel<<<(BB*LLEN*(DDIM/2))/256, 256>>>(q2, delta, b_euler, log_scale, 1);
    euler_kernel<<<(BB*LLEN*(DDIM/2))/256, 256>>>(k2, delta, b_euler, log_scale, 0);

    // 6. attention
    flash_kernel<<<dim3(LLEN/64, BB*NHEAD), 256>>>(q2, k2, v, ctx);

    // 7. output projection
    gemm_tn<<<dim3(DDIM/64, M/64), 256>>>(ctx, Wd, bd, hid, M, DDIM, DDIM);

    // 8. residual + layernorm
    ln_kernel<<<M, 256>>>(hid, X, gamma, beta, out);
}

// round 2
// speedup vs baseline: 1.8292x; 1.8292x over previous
#include <cuda_runtime.h>
#include <cuda_bf16.h>
#include <math.h>

#define BB 2
#define LLEN 2048
#define DDIM 1024
#define NHEAD 16
#define DHEAD 64

// ---------------- scratch (device globals; no allocations allowed) ----------------
__device__ float g_q[BB*LLEN*DDIM];
__device__ float g_k[BB*LLEN*DDIM];
__device__ float g_v[BB*LLEN*DDIM];
__device__ float g_q2[BB*LLEN*DDIM];
__device__ float g_k2[BB*LLEN*DDIM];
__device__ float g_ctx[BB*LLEN*DDIM];
__device__ float g_hid[BB*LLEN*DDIM];
__device__ float g_Pq[BB*DDIM*DDIM];
__device__ float g_Pk[BB*DDIM*DDIM];
__device__ float g_scq[BB*DDIM];
__device__ float g_sck[BB*DDIM];
__device__ float g_partX[BB*16*DDIM];
__device__ float g_meanX[BB*DDIM];
__device__ float g_bsq[BB*DDIM];
__device__ float g_bsk[BB*DDIM];

// ---------------- helpers ----------------
__device__ __forceinline__ unsigned f2tf32(float f) {
    unsigned r;
    asm("cvt.rna.tf32.f32 %0, %1;" : "=r"(r) : "f"(f));
    return r;
}

__device__ __forceinline__ void mma_tf32(float& c0, float& c1, float& c2, float& c3,
                                         unsigned a0, unsigned a1, unsigned a2, unsigned a3,
                                         unsigned b0, unsigned b1)
{
    asm volatile("mma.sync.aligned.m16n8k8.row.col.f32.tf32.tf32.f32 "
                 "{%0,%1,%2,%3}, {%4,%5,%6,%7}, {%8,%9}, {%0,%1,%2,%3};"
                 : "+f"(c0), "+f"(c1), "+f"(c2), "+f"(c3)
                 : "r"(a0), "r"(a1), "r"(a2), "r"(a3), "r"(b0), "r"(b1));
}

// ---------------- TF32 GEMM: C[M,N] = A[M,K] @ Bt[N,K]^T (+bias) ----------------
// block tile 128x128, BK=32, 256 threads = 8 warps, warp tile 64x32.
// smem layout: tile[row][k] with row stride 36 (bank map 4g+c, conflict-free).
__global__ void __launch_bounds__(256, 2)
gemm_tf32(const float* __restrict__ A, const float* __restrict__ Bt,
          const float* __restrict__ bias, float* __restrict__ C,
          int M, int N, int K,
          long long sA, long long sB, long long sC)
{
    __shared__ unsigned As[128 * 36];
    __shared__ unsigned Bs[128 * 36];

    const int tid  = threadIdx.x;
    const int warp = tid >> 5;
    const int lane = tid & 31;
    const int g = lane >> 2;     // 0..7
    const int c = lane & 3;      // 0..3
    const int wm = warp & 1;     // 0..1  (64-row slab)
    const int wn = warp >> 1;    // 0..3  (32-col slab)

    A  += (size_t)blockIdx.z * sA;
    Bt += (size_t)blockIdx.z * sB;
    C  += (size_t)blockIdx.z * sC;

    const int row0 = blockIdx.y * 128;
    const int col0 = blockIdx.x * 128;

    float acc[4][4][4];
#pragma unroll
    for (int i = 0; i < 4; i++)
#pragma unroll
        for (int j = 0; j < 4; j++)
#pragma unroll
            for (int t = 0; t < 4; t++) acc[i][j][t] = 0.f;

    // loader: 128 rows x 8 float4-cols = 1024 slots, 4 per thread
    int lrow[4], lc4[4];
#pragma unroll
    for (int i = 0; i < 4; i++) { int s = tid + i * 256; lrow[i] = s >> 3; lc4[i] = (s & 7) * 4; }

    float4 pa[4], pb[4];
#pragma unroll
    for (int i = 0; i < 4; i++) {
        pa[i] = *(const float4*)&A[(size_t)(row0 + lrow[i]) * K + lc4[i]];
        pb[i] = *(const float4*)&Bt[(size_t)(col0 + lrow[i]) * K + lc4[i]];
    }

    for (int k0 = 0; k0 < K; k0 += 32) {
        __syncthreads();
#pragma unroll
        for (int i = 0; i < 4; i++) {
            uint4 ua = make_uint4(f2tf32(pa[i].x), f2tf32(pa[i].y), f2tf32(pa[i].z), f2tf32(pa[i].w));
            uint4 ub = make_uint4(f2tf32(pb[i].x), f2tf32(pb[i].y), f2tf32(pb[i].z), f2tf32(pb[i].w));
            *(uint4*)&As[lrow[i] * 36 + lc4[i]] = ua;
            *(uint4*)&Bs[lrow[i] * 36 + lc4[i]] = ub;
        }
        __syncthreads();

        if (k0 + 32 < K) {
#pragma unroll
            for (int i = 0; i < 4; i++) {
                pa[i] = *(const float4*)&A[(size_t)(row0 + lrow[i]) * K + k0 + 32 + lc4[i]];
                pb[i] = *(const float4*)&Bt[(size_t)(col0 + lrow[i]) * K + k0 + 32 + lc4[i]];
            }
        }

#pragma unroll
        for (int ks = 0; ks < 4; ks++) {
            const int kk = ks * 8;
            unsigned a[4][4], b[4][2];
#pragma unroll
            for (int i = 0; i < 4; i++) {
                int m = wm * 64 + i * 16 + g;
                a[i][0] = As[m * 36 + kk + c];
                a[i][1] = As[(m + 8) * 36 + kk + c];
                a[i][2] = As[m * 36 + kk + c + 4];
                a[i][3] = As[(m + 8) * 36 + kk + c + 4];
            }
#pragma unroll
            for (int j = 0; j < 4; j++) {
                int n = wn * 32 + j * 8 + g;
                b[j][0] = Bs[n * 36 + kk + c];
                b[j][1] = Bs[n * 36 + kk + c + 4];
            }
#pragma unroll
            for (int i = 0; i < 4; i++)
#pragma unroll
                for (int j = 0; j < 4; j++)
                    mma_tf32(acc[i][j][0], acc[i][j][1], acc[i][j][2], acc[i][j][3],
                             a[i][0], a[i][1], a[i][2], a[i][3], b[j][0], b[j][1]);
        }
    }

    // epilogue: c0:(g,2c) c1:(g,2c+1) c2:(g+8,2c) c3:(g+8,2c+1)
#pragma unroll
    for (int i = 0; i < 4; i++) {
        int r0 = row0 + wm * 64 + i * 16 + g;
#pragma unroll
        for (int j = 0; j < 4; j++) {
            int cc = col0 + wn * 32 + j * 8 + 2 * c;
            float b0 = bias ? bias[cc] : 0.f;
            float b1 = bias ? bias[cc + 1] : 0.f;
            C[(size_t)r0 * N + cc]            = acc[i][j][0] + b0;
            C[(size_t)r0 * N + cc + 1]        = acc[i][j][1] + b1;
            C[(size_t)(r0 + 8) * N + cc]      = acc[i][j][2] + b0;
            C[(size_t)(r0 + 8) * N + cc + 1]  = acc[i][j][3] + b1;
        }
    }
}

// ---------------- column mean over L (two stage) ----------------
__global__ void colmean_part(const float* __restrict__ X, float* __restrict__ part)
{   // grid (B,16), block 1024
    int b = blockIdx.x, gg = blockIdx.y, d = threadIdx.x;
    const float* Xb = X + (size_t)b * LLEN * DDIM;
    float s = 0.f;
    int l0 = gg * (LLEN / 16);
    for (int t = 0; t < LLEN / 16; t++) s += Xb[(size_t)(l0 + t) * DDIM + d];
    part[((size_t)b * 16 + gg) * DDIM + d] = s;
}

__global__ void colmean_fin(const float* __restrict__ part, float* __restrict__ sc)
{   // grid B, block 1024
    int b = blockIdx.x, d = threadIdx.x;
    float s = 0.f;
    for (int gg = 0; gg < 16; gg++) s += part[((size_t)b * 16 + gg) * DDIM + d];
    sc[b * DDIM + d] = s * (1.0f / LLEN);
}

// ---------------- exact scores: sc[b,j] = dot(meanX[b], W[j]) + bias[j] ----------------
__global__ void score_kernel(const float* __restrict__ meanX, const float* __restrict__ W,
                             const float* __restrict__ bias, float* __restrict__ out)
{   // grid (DDIM/8, B), block 256
    __shared__ float mx[DDIM];
    int b = blockIdx.y;
    int tid = threadIdx.x, warp = tid >> 5, lane = tid & 31;
    for (int e = tid; e < DDIM; e += 256) mx[e] = meanX[b * DDIM + e];
    __syncthreads();
    int j = blockIdx.x * 8 + warp;
    const float* Wr = W + (size_t)j * DDIM;
    float s = 0.f;
    for (int kk = lane; kk < DDIM; kk += 32) s += mx[kk] * Wr[kk];
    for (int o = 16; o > 0; o >>= 1) s += __shfl_xor_sync(0xffffffffu, s, o);
    if (lane == 0) out[b * DDIM + j] = s + bias[j];
}

// ---------------- Bsum_j = sum_k |s_j - s_k| ----------------
__global__ void bsum_kernel(const float* __restrict__ sc, float* __restrict__ bs)
{   // grid B, block 1024
    __shared__ float ss[1024];
    int b = blockIdx.x, j = threadIdx.x;
    float sj = sc[b * 1024 + j];
    ss[j] = sj;
    __syncthreads();
    float a = 0.f;
    for (int kk = 0; kk < 1024; kk++) a += fabsf(sj - ss[kk]);
    bs[b * 1024 + j] = a;
}

// ---------------- P[b,i,j] = softmax_j( s_j*(n-1-2i) - Bsum_j ) ----------------
__global__ void sortP_kernel(const float* __restrict__ sc, const float* __restrict__ bs,
                             float* __restrict__ P)
{   // grid (1024, B), block 256
    const int n = 1024;
    int i = blockIdx.x, b = blockIdx.y;
    int tid = threadIdx.x;
    const float* s  = sc + b * n;
    const float* Bv = bs + b * n;
    float scal = (float)(n - 1 - 2 * i);

    float v[4]; float mx = -1e30f;
#pragma unroll
    for (int t = 0; t < 4; t++) {
        int j = tid + t * 256;
        float x = s[j] * scal - Bv[j];
        v[t] = x; mx = fmaxf(mx, x);
    }
    __shared__ float sm[8];
    __shared__ float tot;
    for (int o = 16; o > 0; o >>= 1) mx = fmaxf(mx, __shfl_xor_sync(0xffffffffu, mx, o));
    if ((tid & 31) == 0) sm[tid >> 5] = mx;
    __syncthreads();
    if (tid == 0) { float t2 = sm[0]; for (int w = 1; w < 8; w++) t2 = fmaxf(t2, sm[w]); tot = t2; }
    __syncthreads();
    mx = tot;
    float sum = 0.f;
#pragma unroll
    for (int t = 0; t < 4; t++) { float e = expf(v[t] - mx); v[t] = e; sum += e; }
    __syncthreads();
    for (int o = 16; o > 0; o >>= 1) sum += __shfl_xor_sync(0xffffffffu, sum, o);
    if ((tid & 31) == 0) sm[tid >> 5] = sum;
    __syncthreads();
    if (tid == 0) { float t2 = 0.f; for (int w = 0; w < 8; w++) t2 += sm[w]; tot = t2; }
    __syncthreads();
    float inv = 1.0f / tot;
    float* Pr = P + ((size_t)b * n + i) * n;
#pragma unroll
    for (int t = 0; t < 4; t++) Pr[tid + t * 256] = v[t] * inv;
}

// ---------------- Euler pointwise (in-place, float2 pairs) ----------------
__global__ void euler_kernel(float* __restrict__ X, const float* __restrict__ delta,
                             const float* __restrict__ b_euler, const float* __restrict__ log_scale,
                             int add_b)
{
    int idx = blockIdx.x * blockDim.x + threadIdx.x;
    int i = idx & 511;
    float2 rp = ((float2*)X)[idx];
    float r = rp.x, p = rp.y;
    float lam = sqrtf(r * r + p * p + 1e-6f);
    float th = atan2f(p / lam, r / lam) * delta[i];
    if (add_b) th += b_euler[i];
    float ls = fminf(fmaxf(log_scale[i], -5.f), 5.f);
    lam = lam * expf(ls);
    ((float2*)X)[idx] = make_float2(lam * cosf(th), lam * sinf(th));
}

// ---------------- flash attention (fp32, online softmax) ----------------
__global__ void flash_kernel(const float* __restrict__ Q, const float* __restrict__ K,
                             const float* __restrict__ V, float* __restrict__ O)
{
    __shared__ float qs[64][65];
    __shared__ float ks[32][65];
    __shared__ float vs[32][65];
    __shared__ float ps[64][33];
    __shared__ float redA[64][4];
    __shared__ float redB[64][4];

    const int tid = threadIdx.x;
    const int r  = tid & 63;
    const int cg = tid >> 6;
    const int bh = blockIdx.y;
    const int b = bh >> 4, h = bh & 15;
    const int q0 = blockIdx.x * 64;
    const float* Qb = Q + (size_t)b * LLEN * DDIM + h * DHEAD;
    const float* Kb = K + (size_t)b * LLEN * DDIM + h * DHEAD;
    const float* Vb = V + (size_t)b * LLEN * DDIM + h * DHEAD;

    for (int e = tid; e < 64 * 64; e += 256) {
        int rr = e >> 6, dd = e & 63;
        qs[rr][dd] = Qb[(size_t)(q0 + rr) * DDIM + dd] * 0.125f;
    }

    float o[16];
#pragma unroll
    for (int i = 0; i < 16; i++) o[i] = 0.f;
    float m = -1e30f, l = 0.f;

    for (int k0 = 0; k0 < LLEN; k0 += 32) {
        __syncthreads();
        for (int e = tid; e < 32 * 64; e += 256) {
            int rr = e >> 6, dd = e & 63;
            ks[rr][dd] = Kb[(size_t)(k0 + rr) * DDIM + dd];
            vs[rr][dd] = Vb[(size_t)(k0 + rr) * DDIM + dd];
        }
        __syncthreads();

        float s[8];
#pragma unroll
        for (int j = 0; j < 8; j++) s[j] = 0.f;
        const int c0 = cg * 8;
#pragma unroll 8
        for (int d = 0; d < 64; d++) {
            float qv = qs[r][d];
#pragma unroll
            for (int j = 0; j < 8; j++) s[j] += qv * ks[c0 + j][d];
        }
        float pm = s[0];
#pragma unroll
        for (int j = 1; j < 8; j++) pm = fmaxf(pm, s[j]);
        redA[r][cg] = pm;
        __syncthreads();
        float mn = fmaxf(fmaxf(redA[r][0], redA[r][1]), fmaxf(redA[r][2], redA[r][3]));
        mn = fmaxf(m, mn);
        float psum = 0.f;
#pragma unroll
        for (int j = 0; j < 8; j++) {
            float pv = expf(s[j] - mn);
            ps[r][c0 + j] = pv;
            psum += pv;
        }
        redB[r][cg] = psum;
        __syncthreads();
        float ladd = redB[r][0] + redB[r][1] + redB[r][2] + redB[r][3];
        float scl = expf(m - mn);
        l = l * scl + ladd;
        m = mn;
        const int oc = cg * 16;
#pragma unroll
        for (int i = 0; i < 16; i++) o[i] *= scl;
#pragma unroll 4
        for (int j = 0; j < 32; j++) {
            float pv = ps[r][j];
#pragma unroll
            for (int i = 0; i < 16; i++) o[i] += pv * vs[j][oc + i];
        }
    }
    float inv = 1.0f / l;
    float* Ob = O + (size_t)b * LLEN * DDIM + h * DHEAD;
    const int oc = cg * 16;
#pragma unroll
    for (int i = 0; i < 16; i++)
        Ob[(size_t)(q0 + r) * DDIM + oc + i] = o[i] * inv;
}

// ---------------- residual + LayerNorm ----------------
__global__ void ln_kernel(const float* __restrict__ hid, const float* __restrict__ inp,
                          const float* __restrict__ gamma, const float* __restrict__ beta,
                          float* __restrict__ out)
{
    size_t row = blockIdx.x;
    int tid = threadIdx.x;
    float x[4];
    float s = 0.f;
#pragma unroll
    for (int t = 0; t < 4; t++) {
        int d = tid + t * 256;
        x[t] = hid[row * DDIM + d] + inp[row * DDIM + d];
        s += x[t];
    }
    __shared__ float sm[8];
    __shared__ float tot;
    for (int o = 16; o > 0; o >>= 1) s += __shfl_xor_sync(0xffffffffu, s, o);
    if ((tid & 31) == 0) sm[tid >> 5] = s;
    __syncthreads();
    if (tid == 0) { float t2 = 0.f; for (int w = 0; w < 8; w++) t2 += sm[w]; tot = t2; }
    __syncthreads();
    float mu = tot * (1.0f / DDIM);
    float vsum = 0.f;
#pragma unroll
    for (int t = 0; t < 4; t++) { float dd = x[t] - mu; vsum += dd * dd; }
    __syncthreads();
    for (int o = 16; o > 0; o >>= 1) vsum += __shfl_xor_sync(0xffffffffu, vsum, o);
    if ((tid & 31) == 0) sm[tid >> 5] = vsum;
    __syncthreads();
    if (tid == 0) { float t2 = 0.f; for (int w = 0; w < 8; w++) t2 += sm[w]; tot = t2; }
    __syncthreads();
    float var = tot * (1.0f / DDIM);
    float inv = 1.0f / sqrtf(var + 1e-12f);
#pragma unroll
    for (int t = 0; t < 4; t++) {
        int d = tid + t * 256;
        out[row * DDIM + d] = (x[t] - mu) * inv * gamma[d] + beta[d];
    }
}

// ---------------- driver ----------------
extern "C" void kernel_launch(void* const* d_in, const int* in_sizes, int n_in,
                              void* d_out, int out_size)
{
    const float* X   = (const float*)d_in[0];
    const float* Wq  = (const float*)d_in[1];
    const float* bq  = (const float*)d_in[2];
    const float* Wk  = (const float*)d_in[3];
    const float* bk  = (const float*)d_in[4];
    const float* Wv  = (const float*)d_in[5];
    const float* bv  = (const float*)d_in[6];
    const float* Wd  = (const float*)d_in[7];
    const float* bd  = (const float*)d_in[8];
    const float* gamma     = (const float*)d_in[9];
    const float* beta      = (const float*)d_in[10];
    const float* delta     = (const float*)d_in[11];
    const float* b_euler   = (const float*)d_in[12];
    const float* log_scale = (const float*)d_in[13];
    float* out = (float*)d_out;

    float *q, *k, *v, *q2, *k2, *ctx, *hid, *Pq, *Pk, *scq, *sck, *pX, *meanX, *bsq, *bsk;
    { void* p;
      cudaGetSymbolAddress(&p, g_q);     q     = (float*)p;
      cudaGetSymbolAddress(&p, g_k);     k     = (float*)p;
      cudaGetSymbolAddress(&p, g_v);     v     = (float*)p;
      cudaGetSymbolAddress(&p, g_q2);    q2    = (float*)p;
      cudaGetSymbolAddress(&p, g_k2);    k2    = (float*)p;
      cudaGetSymbolAddress(&p, g_ctx);   ctx   = (float*)p;
      cudaGetSymbolAddress(&p, g_hid);   hid   = (float*)p;
      cudaGetSymbolAddress(&p, g_Pq);    Pq    = (float*)p;
      cudaGetSymbolAddress(&p, g_Pk);    Pk    = (float*)p;
      cudaGetSymbolAddress(&p, g_scq);   scq   = (float*)p;
      cudaGetSymbolAddress(&p, g_sck);   sck   = (float*)p;
      cudaGetSymbolAddress(&p, g_partX); pX    = (float*)p;
      cudaGetSymbolAddress(&p, g_meanX); meanX = (float*)p;
      cudaGetSymbolAddress(&p, g_bsq);   bsq   = (float*)p;
      cudaGetSymbolAddress(&p, g_bsk);   bsk   = (float*)p;
    }

    const int M = BB * LLEN;   // 4096

    // exact scores path (fp32): meanX then tiny GEMV per W
    colmean_part<<<dim3(BB, 16), 1024>>>(X, pX);
    colmean_fin<<<BB, 1024>>>(pX, meanX);
    score_kernel<<<dim3(DDIM / 8, BB), 256>>>(meanX, Wq, bq, scq);
    score_kernel<<<dim3(DDIM / 8, BB), 256>>>(meanX, Wk, bk, sck);

    // projections (tf32 tensor core)
    gemm_tf32<<<dim3(DDIM/128, M/128, 1), 256>>>(X, Wq, bq, q, M, DDIM, DDIM, 0, 0, 0);
    gemm_tf32<<<dim3(DDIM/128, M/128, 1), 256>>>(X, Wk, bk, k, M, DDIM, DDIM, 0, 0, 0);
    gemm_tf32<<<dim3(DDIM/128, M/128, 1), 256>>>(X, Wv, bv, v, M, DDIM, DDIM, 0, 0, 0);

    // neural sort permutation matrices (fp32-exact scores)
    bsum_kernel<<<BB, 1024>>>(scq, bsq);
    bsum_kernel<<<BB, 1024>>>(sck, bsk);
    sortP_kernel<<<dim3(DDIM, BB), 256>>>(scq, bsq, Pq);
    sortP_kernel<<<dim3(DDIM, BB), 256>>>(sck, bsk, Pk);

    // v_sorted = x @ P^T  (batched tf32)
    gemm_tf32<<<dim3(DDIM/128, LLEN/128, BB), 256>>>(q, Pq, nullptr, q2, LLEN, DDIM, DDIM,
                                                     (long long)LLEN*DDIM, (long long)DDIM*DDIM, (long long)LLEN*DDIM);
    gemm_tf32<<<dim3(DDIM/128, LLEN/128, BB), 256>>>(k, Pk, nullptr, k2, LLEN, DDIM, DDIM,
                                                     (long long)LLEN*DDIM, (long long)DDIM*DDIM, (long long)LLEN*DDIM);

    // euler pointwise (in place)
    euler_kernel<<<(BB*LLEN*(DDIM/2))/256, 256>>>(q2, delta, b_euler, log_scale, 1);
    euler_kernel<<<(BB*LLEN*(DDIM/2))/256, 256>>>(k2, delta, b_euler, log_scale, 0);

    // attention
    flash_kernel<<<dim3(LLEN/64, BB*NHEAD), 256>>>(q2, k2, v, ctx);

    // output projection
    gemm_tf32<<<dim3(DDIM/128, M/128, 1), 256>>>(ctx, Wd, bd, hid, M, DDIM, DDIM, 0, 0, 0);

    // residual + layernorm
    ln_kernel<<<M, 256>>>(hid, X, gamma, beta, out);
}

// round 7
// speedup vs baseline: 4.0503x; 2.2142x over previous
#include <cuda_runtime.h>
#include <cuda_bf16.h>
#include <math.h>

#define BB 2
#define LLEN 2048
#define DDIM 1024
#define NHEAD 16
#define DHEAD 64

// ---------------- scratch (device globals; no allocations allowed) ----------------
__device__ float g_q[BB*LLEN*DDIM];
__device__ float g_k[BB*LLEN*DDIM];
__device__ float g_v[BB*LLEN*DDIM];
__device__ float g_q2[BB*LLEN*DDIM];
__device__ float g_k2[BB*LLEN*DDIM];
__device__ float g_ctx[BB*LLEN*DDIM];
__device__ float g_hid[BB*LLEN*DDIM];
__device__ float g_Pq[BB*DDIM*DDIM];
__device__ float g_Pk[BB*DDIM*DDIM];
__device__ float g_scq[BB*DDIM];
__device__ float g_sck[BB*DDIM];
__device__ float g_partX[BB*16*DDIM];
__device__ float g_meanX[BB*DDIM];
__device__ float g_bsq[BB*DDIM];
__device__ float g_bsk[BB*DDIM];

// ---------------- helpers ----------------
__device__ __forceinline__ unsigned f2tf32(float f) {
    unsigned r;
    asm("cvt.rna.tf32.f32 %0, %1;" : "=r"(r) : "f"(f));
    return r;
}

__device__ __forceinline__ void mma_tf32(float& c0, float& c1, float& c2, float& c3,
                                         unsigned a0, unsigned a1, unsigned a2, unsigned a3,
                                         unsigned b0, unsigned b1)
{
    asm volatile("mma.sync.aligned.m16n8k8.row.col.f32.tf32.tf32.f32 "
                 "{%0,%1,%2,%3}, {%4,%5,%6,%7}, {%8,%9}, {%0,%1,%2,%3};"
                 : "+f"(c0), "+f"(c1), "+f"(c2), "+f"(c3)
                 : "r"(a0), "r"(a1), "r"(a2), "r"(a3), "r"(b0), "r"(b1));
}

// ---------------- TF32 GEMM: C[M,N] = A[M,K] @ Bt[N,K]^T (+bias) ----------------
__global__ void __launch_bounds__(256, 2)
gemm_tf32(const float* __restrict__ A, const float* __restrict__ Bt,
          const float* __restrict__ bias, float* __restrict__ C,
          int M, int N, int K,
          long long sA, long long sB, long long sC)
{
    __shared__ unsigned As[128 * 36];
    __shared__ unsigned Bs[128 * 36];

    const int tid  = threadIdx.x;
    const int warp = tid >> 5;
    const int lane = tid & 31;
    const int g = lane >> 2;
    const int c = lane & 3;
    const int wm = warp & 1;
    const int wn = warp >> 1;

    A  += (size_t)blockIdx.z * sA;
    Bt += (size_t)blockIdx.z * sB;
    C  += (size_t)blockIdx.z * sC;

    const int row0 = blockIdx.y * 128;
    const int col0 = blockIdx.x * 128;

    float acc[4][4][4];
#pragma unroll
    for (int i = 0; i < 4; i++)
#pragma unroll
        for (int j = 0; j < 4; j++)
#pragma unroll
            for (int t = 0; t < 4; t++) acc[i][j][t] = 0.f;

    int lrow[4], lc4[4];
#pragma unroll
    for (int i = 0; i < 4; i++) { int s = tid + i * 256; lrow[i] = s >> 3; lc4[i] = (s & 7) * 4; }

    float4 pa[4], pb[4];
#pragma unroll
    for (int i = 0; i < 4; i++) {
        pa[i] = *(const float4*)&A[(size_t)(row0 + lrow[i]) * K + lc4[i]];
        pb[i] = *(const float4*)&Bt[(size_t)(col0 + lrow[i]) * K + lc4[i]];
    }

    for (int k0 = 0; k0 < K; k0 += 32) {
        __syncthreads();
#pragma unroll
        for (int i = 0; i < 4; i++) {
            uint4 ua = make_uint4(f2tf32(pa[i].x), f2tf32(pa[i].y), f2tf32(pa[i].z), f2tf32(pa[i].w));
            uint4 ub = make_uint4(f2tf32(pb[i].x), f2tf32(pb[i].y), f2tf32(pb[i].z), f2tf32(pb[i].w));
            *(uint4*)&As[lrow[i] * 36 + lc4[i]] = ua;
            *(uint4*)&Bs[lrow[i] * 36 + lc4[i]] = ub;
        }
        __syncthreads();

        if (k0 + 32 < K) {
#pragma unroll
            for (int i = 0; i < 4; i++) {
                pa[i] = *(const float4*)&A[(size_t)(row0 + lrow[i]) * K + k0 + 32 + lc4[i]];
                pb[i] = *(const float4*)&Bt[(size_t)(col0 + lrow[i]) * K + k0 + 32 + lc4[i]];
            }
        }

#pragma unroll
        for (int ks = 0; ks < 4; ks++) {
            const int kk = ks * 8;
            unsigned a[4][4], b[4][2];
#pragma unroll
            for (int i = 0; i < 4; i++) {
                int m = wm * 64 + i * 16 + g;
                a[i][0] = As[m * 36 + kk + c];
                a[i][1] = As[(m + 8) * 36 + kk + c];
                a[i][2] = As[m * 36 + kk + c + 4];
                a[i][3] = As[(m + 8) * 36 + kk + c + 4];
            }
#pragma unroll
            for (int j = 0; j < 4; j++) {
                int n = wn * 32 + j * 8 + g;
                b[j][0] = Bs[n * 36 + kk + c];
                b[j][1] = Bs[n * 36 + kk + c + 4];
            }
#pragma unroll
            for (int i = 0; i < 4; i++)
#pragma unroll
                for (int j = 0; j < 4; j++)
                    mma_tf32(acc[i][j][0], acc[i][j][1], acc[i][j][2], acc[i][j][3],
                             a[i][0], a[i][1], a[i][2], a[i][3], b[j][0], b[j][1]);
        }
    }

#pragma unroll
    for (int i = 0; i < 4; i++) {
        int r0 = row0 + wm * 64 + i * 16 + g;
#pragma unroll
        for (int j = 0; j < 4; j++) {
            int cc = col0 + wn * 32 + j * 8 + 2 * c;
            float b0 = bias ? bias[cc] : 0.f;
            float b1 = bias ? bias[cc + 1] : 0.f;
            C[(size_t)r0 * N + cc]            = acc[i][j][0] + b0;
            C[(size_t)r0 * N + cc + 1]        = acc[i][j][1] + b1;
            C[(size_t)(r0 + 8) * N + cc]      = acc[i][j][2] + b0;
            C[(size_t)(r0 + 8) * N + cc + 1]  = acc[i][j][3] + b1;
        }
    }
}

// ---------------- column mean over L (two stage) ----------------
__global__ void colmean_part(const float* __restrict__ X, float* __restrict__ part)
{
    int b = blockIdx.x, gg = blockIdx.y, d = threadIdx.x;
    const float* Xb = X + (size_t)b * LLEN * DDIM;
    float s = 0.f;
    int l0 = gg * (LLEN / 16);
    for (int t = 0; t < LLEN / 16; t++) s += Xb[(size_t)(l0 + t) * DDIM + d];
    part[((size_t)b * 16 + gg) * DDIM + d] = s;
}

__global__ void colmean_fin(const float* __restrict__ part, float* __restrict__ sc)
{
    int b = blockIdx.x, d = threadIdx.x;
    float s = 0.f;
    for (int gg = 0; gg < 16; gg++) s += part[((size_t)b * 16 + gg) * DDIM + d];
    sc[b * DDIM + d] = s * (1.0f / LLEN);
}

// ---------------- exact scores: sc[b,j] = dot(meanX[b], W[j]) + bias[j] ----------------
__global__ void score_kernel(const float* __restrict__ meanX, const float* __restrict__ W,
                             const float* __restrict__ bias, float* __restrict__ out)
{
    __shared__ float mx[DDIM];
    int b = blockIdx.y;
    int tid = threadIdx.x, warp = tid >> 5, lane = tid & 31;
    for (int e = tid; e < DDIM; e += 256) mx[e] = meanX[b * DDIM + e];
    __syncthreads();
    int j = blockIdx.x * 8 + warp;
    const float* Wr = W + (size_t)j * DDIM;
    float s = 0.f;
    for (int kk = lane; kk < DDIM; kk += 32) s += mx[kk] * Wr[kk];
    for (int o = 16; o > 0; o >>= 1) s += __shfl_xor_sync(0xffffffffu, s, o);
    if (lane == 0) out[b * DDIM + j] = s + bias[j];
}

// ---------------- Bsum_j = sum_k |s_j - s_k| ----------------
__global__ void bsum_kernel(const float* __restrict__ sc, float* __restrict__ bs)
{
    __shared__ float ss[1024];
    int b = blockIdx.x, j = threadIdx.x;
    float sj = sc[b * 1024 + j];
    ss[j] = sj;
    __syncthreads();
    float a = 0.f;
    for (int kk = 0; kk < 1024; kk++) a += fabsf(sj - ss[kk]);
    bs[b * 1024 + j] = a;
}

// ---------------- P[b,i,j] = softmax_j( s_j*(n-1-2i) - Bsum_j ) ----------------
__global__ void sortP_kernel(const float* __restrict__ sc, const float* __restrict__ bs,
                             float* __restrict__ P)
{
    const int n = 1024;
    int i = blockIdx.x, b = blockIdx.y;
    int tid = threadIdx.x;
    const float* s  = sc + b * n;
    const float* Bv = bs + b * n;
    float scal = (float)(n - 1 - 2 * i);

    float v[4]; float mx = -1e30f;
#pragma unroll
    for (int t = 0; t < 4; t++) {
        int j = tid + t * 256;
        float x = s[j] * scal - Bv[j];
        v[t] = x; mx = fmaxf(mx, x);
    }
    __shared__ float sm[8];
    __shared__ float tot;
    for (int o = 16; o > 0; o >>= 1) mx = fmaxf(mx, __shfl_xor_sync(0xffffffffu, mx, o));
    if ((tid & 31) == 0) sm[tid >> 5] = mx;
    __syncthreads();
    if (tid == 0) { float t2 = sm[0]; for (int w = 1; w < 8; w++) t2 = fmaxf(t2, sm[w]); tot = t2; }
    __syncthreads();
    mx = tot;
    float sum = 0.f;
#pragma unroll
    for (int t = 0; t < 4; t++) { float e = expf(v[t] - mx); v[t] = e; sum += e; }
    __syncthreads();
    for (int o = 16; o > 0; o >>= 1) sum += __shfl_xor_sync(0xffffffffu, sum, o);
    if ((tid & 31) == 0) sm[tid >> 5] = sum;
    __syncthreads();
    if (tid == 0) { float t2 = 0.f; for (int w = 0; w < 8; w++) t2 += sm[w]; tot = t2; }
    __syncthreads();
    float inv = 1.0f / tot;
    float* Pr = P + ((size_t)b * n + i) * n;
#pragma unroll
    for (int t = 0; t < 4; t++) Pr[tid + t * 256] = v[t] * inv;
}

// ---------------- Euler pointwise (in-place, float2 pairs) ----------------
__global__ void euler_kernel(float* __restrict__ X, const float* __restrict__ delta,
                             const float* __restrict__ b_euler, const float* __restrict__ log_scale,
                             int add_b)
{
    int idx = blockIdx.x * blockDim.x + threadIdx.x;
    int i = idx & 511;
    float2 rp = ((float2*)X)[idx];
    float r = rp.x, p = rp.y;
    float lam = sqrtf(r * r + p * p + 1e-6f);
    float th = atan2f(p / lam, r / lam) * delta[i];
    if (add_b) th += b_euler[i];
    float ls = fminf(fmaxf(log_scale[i], -5.f), 5.f);
    lam = lam * expf(ls);
    ((float2*)X)[idx] = make_float2(lam * cosf(th), lam * sinf(th));
}

// ---------------- flash attention (tf32 tensor core, online softmax) ----------------
// grid (L/128, B*H), block 256 = 8 warps; warp owns 16 q rows; K/V tile = 64.
__global__ void __launch_bounds__(256, 1)
flash_tf32(const float* __restrict__ Q, const float* __restrict__ K,
           const float* __restrict__ V, float* __restrict__ O)
{
    __shared__ unsigned ks[64 * 68];   // [key][d]  stride 68: banks 4g+c, conflict-free
    __shared__ unsigned vs[64 * 72];   // [key][d]  stride 72: banks 8c+g, conflict-free

    const int tid  = threadIdx.x;
    const int warp = tid >> 5;
    const int lane = tid & 31;
    const int g = lane >> 2;
    const int c = lane & 3;
    const int bh = blockIdx.y;
    const int b = bh >> 4, h = bh & 15;
    const int q0 = blockIdx.x * 128 + warp * 16;

    const float* Qb = Q + (size_t)b * LLEN * DDIM + h * DHEAD;
    const float* Kb = K + (size_t)b * LLEN * DDIM + h * DHEAD;
    const float* Vb = V + (size_t)b * LLEN * DDIM + h * DHEAD;
    float* Ob       = O + (size_t)b * LLEN * DDIM + h * DHEAD;

    // Q fragments in registers (scaled by 1/sqrt(64)), 8 k-chunks of 8
    unsigned qf[8][4];
#pragma unroll
    for (int kc = 0; kc < 8; kc++) {
        qf[kc][0] = f2tf32(Qb[(size_t)(q0 + g)     * DDIM + kc * 8 + c]     * 0.125f);
        qf[kc][1] = f2tf32(Qb[(size_t)(q0 + g + 8) * DDIM + kc * 8 + c]     * 0.125f);
        qf[kc][2] = f2tf32(Qb[(size_t)(q0 + g)     * DDIM + kc * 8 + c + 4] * 0.125f);
        qf[kc][3] = f2tf32(Qb[(size_t)(q0 + g + 8) * DDIM + kc * 8 + c + 4] * 0.125f);
    }

    float o[8][4];
#pragma unroll
    for (int j = 0; j < 8; j++)
#pragma unroll
        for (int t = 0; t < 4; t++) o[j][t] = 0.f;
    float m0 = -1e30f, m8 = -1e30f, l0 = 0.f, l8 = 0.f;

    for (int k0 = 0; k0 < LLEN; k0 += 64) {
        __syncthreads();
        // load K,V tile: 64 rows x 16 float4-cols = 1024 slots, 4 per thread
#pragma unroll
        for (int i = 0; i < 4; i++) {
            int slot = tid + i * 256;          // 0..1023
            int row = slot >> 4, c4 = (slot & 15) * 4;
            float4 kk4 = *(const float4*)&Kb[(size_t)(k0 + row) * DDIM + c4];
            float4 vv4 = *(const float4*)&Vb[(size_t)(k0 + row) * DDIM + c4];
            *(uint4*)&ks[row * 68 + c4] = make_uint4(f2tf32(kk4.x), f2tf32(kk4.y), f2tf32(kk4.z), f2tf32(kk4.w));
            *(uint4*)&vs[row * 72 + c4] = make_uint4(f2tf32(vv4.x), f2tf32(vv4.y), f2tf32(vv4.z), f2tf32(vv4.w));
        }
        __syncthreads();

        // S = Q K^T  (16x64 per warp)
        float s[8][4];
#pragma unroll
        for (int j = 0; j < 8; j++)
#pragma unroll
            for (int t = 0; t < 4; t++) s[j][t] = 0.f;
#pragma unroll
        for (int kc = 0; kc < 8; kc++) {
#pragma unroll
            for (int j = 0; j < 8; j++) {
                unsigned b0 = ks[(j * 8 + g) * 68 + kc * 8 + c];
                unsigned b1 = ks[(j * 8 + g) * 68 + kc * 8 + c + 4];
                mma_tf32(s[j][0], s[j][1], s[j][2], s[j][3],
                         qf[kc][0], qf[kc][1], qf[kc][2], qf[kc][3], b0, b1);
            }
        }

        // online softmax (rows g and g+8, reductions within c-quad)
        float tm0 = -1e30f, tm8 = -1e30f;
#pragma unroll
        for (int j = 0; j < 8; j++) {
            tm0 = fmaxf(tm0, fmaxf(s[j][0], s[j][1]));
            tm8 = fmaxf(tm8, fmaxf(s[j][2], s[j][3]));
        }
        tm0 = fmaxf(tm0, __shfl_xor_sync(0xffffffffu, tm0, 1));
        tm0 = fmaxf(tm0, __shfl_xor_sync(0xffffffffu, tm0, 2));
        tm8 = fmaxf(tm8, __shfl_xor_sync(0xffffffffu, tm8, 1));
        tm8 = fmaxf(tm8, __shfl_xor_sync(0xffffffffu, tm8, 2));

        float mn0 = fmaxf(m0, tm0), mn8 = fmaxf(m8, tm8);
        float sc0 = __expf(m0 - mn0), sc8 = __expf(m8 - mn8);
        m0 = mn0; m8 = mn8;

        float rs0 = 0.f, rs8 = 0.f;
#pragma unroll
        for (int j = 0; j < 8; j++) {
            s[j][0] = __expf(s[j][0] - mn0);
            s[j][1] = __expf(s[j][1] - mn0);
            s[j][2] = __expf(s[j][2] - mn8);
            s[j][3] = __expf(s[j][3] - mn8);
            rs0 += s[j][0] + s[j][1];
            rs8 += s[j][2] + s[j][3];
        }
        rs0 += __shfl_xor_sync(0xffffffffu, rs0, 1);
        rs0 += __shfl_xor_sync(0xffffffffu, rs0, 2);
        rs8 += __shfl_xor_sync(0xffffffffu, rs8, 1);
        rs8 += __shfl_xor_sync(0xffffffffu, rs8, 2);
        l0 = l0 * sc0 + rs0;
        l8 = l8 * sc8 + rs8;

#pragma unroll
        for (int j = 0; j < 8; j++) {
            o[j][0] *= sc0; o[j][1] *= sc0;
            o[j][2] *= sc8; o[j][3] *= sc8;
        }

        // O += P V : relayout P frags (C-layout -> A-layout) via quad shuffles
        const int src0 = (lane & ~3) | (c >> 1);
        const bool odd = (c & 1);
#pragma unroll
        for (int kc = 0; kc < 8; kc++) {
            float u0 = __shfl_sync(0xffffffffu, s[kc][0], src0);
            float u1 = __shfl_sync(0xffffffffu, s[kc][1], src0);
            float w0 = __shfl_sync(0xffffffffu, s[kc][0], src0 + 2);
            float w1 = __shfl_sync(0xffffffffu, s[kc][1], src0 + 2);
            float x0 = __shfl_sync(0xffffffffu, s[kc][2], src0);
            float x1 = __shfl_sync(0xffffffffu, s[kc][3], src0);
            float y0 = __shfl_sync(0xffffffffu, s[kc][2], src0 + 2);
            float y1 = __shfl_sync(0xffffffffu, s[kc][3], src0 + 2);
            unsigned a0 = f2tf32(odd ? u1 : u0);
            unsigned a2 = f2tf32(odd ? w1 : w0);
            unsigned a1 = f2tf32(odd ? x1 : x0);
            unsigned a3 = f2tf32(odd ? y1 : y0);
#pragma unroll
            for (int j = 0; j < 8; j++) {
                unsigned b0 = vs[(kc * 8 + c)     * 72 + j * 8 + g];
                unsigned b1 = vs[(kc * 8 + c + 4) * 72 + j * 8 + g];
                mma_tf32(o[j][0], o[j][1], o[j][2], o[j][3], a0, a1, a2, a3, b0, b1);
            }
        }
    }

    float inv0 = 1.0f / l0, inv8 = 1.0f / l8;
#pragma unroll
    for (int j = 0; j < 8; j++) {
        int cc = j * 8 + 2 * c;
        *(float2*)&Ob[(size_t)(q0 + g)     * DDIM + cc] = make_float2(o[j][0] * inv0, o[j][1] * inv0);
        *(float2*)&Ob[(size_t)(q0 + g + 8) * DDIM + cc] = make_float2(o[j][2] * inv8, o[j][3] * inv8);
    }
}

// ---------------- residual + LayerNorm ----------------
__global__ void ln_kernel(const float* __restrict__ hid, const float* __restrict__ inp,
                          const float* __restrict__ gamma, const float* __restrict__ beta,
                          float* __restrict__ out)
{
    size_t row = blockIdx.x;
    int tid = threadIdx.x;
    float x[4];
    float s = 0.f;
#pragma unroll
    for (int t = 0; t < 4; t++) {
        int d = tid + t * 256;
        x[t] = hid[row * DDIM + d] + inp[row * DDIM + d];
        s += x[t];
    }
    __shared__ float sm[8];
    __shared__ float tot;
    for (int o = 16; o > 0; o >>= 1) s += __shfl_xor_sync(0xffffffffu, s, o);
    if ((tid & 31) == 0) sm[tid >> 5] = s;
    __syncthreads();
    if (tid == 0) { float t2 = 0.f; for (int w = 0; w < 8; w++) t2 += sm[w]; tot = t2; }
    __syncthreads();
    float mu = tot * (1.0f / DDIM);
    float vsum = 0.f;
#pragma unroll
    for (int t = 0; t < 4; t++) { float dd = x[t] - mu; vsum += dd * dd; }
    __syncthreads();
    for (int o = 16; o > 0; o >>= 1) vsum += __shfl_xor_sync(0xffffffffu, vsum, o);
    if ((tid & 31) == 0) sm[tid >> 5] = vsum;
    __syncthreads();
    if (tid == 0) { float t2 = 0.f; for (int w = 0; w < 8; w++) t2 += sm[w]; tot = t2; }
    __syncthreads();
    float var = tot * (1.0f / DDIM);
    float inv = 1.0f / sqrtf(var + 1e-12f);
#pragma unroll
    for (int t = 0; t < 4; t++) {
        int d = tid + t * 256;
        out[row * DDIM + d] = (x[t] - mu) * inv * gamma[d] + beta[d];
    }
}

// ---------------- driver ----------------
extern "C" void kernel_launch(void* const* d_in, const int* in_sizes, int n_in,
                              void* d_out, int out_size)
{
    const float* X   = (const float*)d_in[0];
    const float* Wq  = (const float*)d_in[1];
    const float* bq  = (const float*)d_in[2];
    const float* Wk  = (const float*)d_in[3];
    const float* bk  = (const float*)d_in[4];
    const float* Wv  = (const float*)d_in[5];
    const float* bv  = (const float*)d_in[6];
    const float* Wd  = (const float*)d_in[7];
    const float* bd  = (const float*)d_in[8];
    const float* gamma     = (const float*)d_in[9];
    const float* beta      = (const float*)d_in[10];
    const float* delta     = (const float*)d_in[11];
    const float* b_euler   = (const float*)d_in[12];
    const float* log_scale = (const float*)d_in[13];
    float* out = (float*)d_out;

    float *q, *k, *v, *q2, *k2, *ctx, *hid, *Pq, *Pk, *scq, *sck, *pX, *meanX, *bsq, *bsk;
    { void* p;
      cudaGetSymbolAddress(&p, g_q);     q     = (float*)p;
      cudaGetSymbolAddress(&p, g_k);     k     = (float*)p;
      cudaGetSymbolAddress(&p, g_v);     v     = (float*)p;
      cudaGetSymbolAddress(&p, g_q2);    q2    = (float*)p;
      cudaGetSymbolAddress(&p, g_k2);    k2    = (float*)p;
      cudaGetSymbolAddress(&p, g_ctx);   ctx   = (float*)p;
      cudaGetSymbolAddress(&p, g_hid);   hid   = (float*)p;
      cudaGetSymbolAddress(&p, g_Pq);    Pq    = (float*)p;
      cudaGetSymbolAddress(&p, g_Pk);    Pk    = (float*)p;
      cudaGetSymbolAddress(&p, g_scq);   scq   = (float*)p;
      cudaGetSymbolAddress(&p, g_sck);   sck   = (float*)p;
      cudaGetSymbolAddress(&p, g_partX); pX    = (float*)p;
      cudaGetSymbolAddress(&p, g_meanX); meanX = (float*)p;
      cudaGetSymbolAddress(&p, g_bsq);   bsq   = (float*)p;
      cudaGetSymbolAddress(&p, g_bsk);   bsk   = (float*)p;
    }

    const int M = BB * LLEN;   // 4096

    // exact scores path (fp32)
    colmean_part<<<dim3(BB, 16), 1024>>>(X, pX);
    colmean_fin<<<BB, 1024>>>(pX, meanX);
    score_kernel<<<dim3(DDIM / 8, BB), 256>>>(meanX, Wq, bq, scq);
    score_kernel<<<dim3(DDIM / 8, BB), 256>>>(meanX, Wk, bk, sck);

    // projections (tf32 tensor core)
    gemm_tf32<<<dim3(DDIM/128, M/128, 1), 256>>>(X, Wq, bq, q, M, DDIM, DDIM, 0, 0, 0);
    gemm_tf32<<<dim3(DDIM/128, M/128, 1), 256>>>(X, Wk, bk, k, M, DDIM, DDIM, 0, 0, 0);
    gemm_tf32<<<dim3(DDIM/128, M/128, 1), 256>>>(X, Wv, bv, v, M, DDIM, DDIM, 0, 0, 0);

    // neural sort permutation matrices (fp32-exact scores)
    bsum_kernel<<<BB, 1024>>>(scq, bsq);
    bsum_kernel<<<BB, 1024>>>(sck, bsk);
    sortP_kernel<<<dim3(DDIM, BB), 256>>>(scq, bsq, Pq);
    sortP_kernel<<<dim3(DDIM, BB), 256>>>(sck, bsk, Pk);

    // v_sorted = x @ P^T  (batched tf32)
    gemm_tf32<<<dim3(DDIM/128, LLEN/128, BB), 256>>>(q, Pq, nullptr, q2, LLEN, DDIM, DDIM,
                                                     (long long)LLEN*DDIM, (long long)DDIM*DDIM, (long long)LLEN*DDIM);
    gemm_tf32<<<dim3(DDIM/128, LLEN/128, BB), 256>>>(k, Pk, nullptr, k2, LLEN, DDIM, DDIM,
                                                     (long long)LLEN*DDIM, (long long)DDIM*DDIM, (long long)LLEN*DDIM);

    // euler pointwise (in place)
    euler_kernel<<<(BB*LLEN*(DDIM/2))/256, 256>>>(q2, delta, b_euler, log_scale, 1);
    euler_kernel<<<(BB*LLEN*(DDIM/2))/256, 256>>>(k2, delta, b_euler, log_scale, 0);

    // attention (tf32 tensor core flash)
    flash_tf32<<<dim3(LLEN/128, BB*NHEAD), 256>>>(q2, k2, v, ctx);

    // output projection
    gemm_tf32<<<dim3(DDIM/128, M/128, 1), 256>>>(ctx, Wd, bd, hid, M, DDIM, DDIM, 0, 0, 0);

    // residual + layernorm
    ln_kernel<<<M, 256>>>(hid, X, gamma, beta, out);
}

// round 9
// speedup vs baseline: 4.9195x; 1.2146x over previous
#include <cuda_runtime.h>
#include <cuda_bf16.h>
#include <math.h>

#define BB 2
#define LLEN 2048
#define DDIM 1024
#define NHEAD 16
#define DHEAD 64

// ---------------- scratch (device globals; no allocations allowed) ----------------
__device__ float g_q[BB*LLEN*DDIM];
__device__ float g_k[BB*LLEN*DDIM];
__device__ float g_v[BB*LLEN*DDIM];
__device__ float g_q2[BB*LLEN*DDIM];
__device__ float g_k2[BB*LLEN*DDIM];
__device__ float g_ctx[BB*LLEN*DDIM];
__device__ float g_hid[BB*LLEN*DDIM];
__device__ float g_Pq[BB*DDIM*DDIM];
__device__ float g_Pk[BB*DDIM*DDIM];
__device__ float g_scq[BB*DDIM];
__device__ float g_sck[BB*DDIM];
__device__ float g_partX[BB*16*DDIM];
__device__ float g_meanX[BB*DDIM];
__device__ float g_bsq[BB*DDIM];
__device__ float g_bsk[BB*DDIM];

// ---------------- helpers ----------------
__device__ __forceinline__ unsigned f2tf32(float f) {
    unsigned r;
    asm("cvt.rna.tf32.f32 %0, %1;" : "=r"(r) : "f"(f));
    return r;
}

__device__ __forceinline__ void mma_tf32(float& c0, float& c1, float& c2, float& c3,
                                         unsigned a0, unsigned a1, unsigned a2, unsigned a3,
                                         unsigned b0, unsigned b1)
{
    asm volatile("mma.sync.aligned.m16n8k8.row.col.f32.tf32.tf32.f32 "
                 "{%0,%1,%2,%3}, {%4,%5,%6,%7}, {%8,%9}, {%0,%1,%2,%3};"
                 : "+f"(c0), "+f"(c1), "+f"(c2), "+f"(c3)
                 : "r"(a0), "r"(a1), "r"(a2), "r"(a3), "r"(b0), "r"(b1));
}

__device__ __forceinline__ void mma_bf16(float& c0, float& c1, float& c2, float& c3,
                                         unsigned a0, unsigned a1, unsigned a2, unsigned a3,
                                         unsigned b0, unsigned b1)
{
    asm volatile("mma.sync.aligned.m16n8k16.row.col.f32.bf16.bf16.f32 "
                 "{%0,%1,%2,%3}, {%4,%5,%6,%7}, {%8,%9}, {%0,%1,%2,%3};"
                 : "+f"(c0), "+f"(c1), "+f"(c2), "+f"(c3)
                 : "r"(a0), "r"(a1), "r"(a2), "r"(a3), "r"(b0), "r"(b1));
}

__device__ __forceinline__ unsigned pack_bf16(float lo, float hi) {
    __nv_bfloat162 t = __floats2bfloat162_rn(lo, hi);   // .x = lo half, .y = hi half
    return *(unsigned*)&t;
}

// ---------------- BF16 GEMM: C[M,N] = A[M,K] @ Bt[N,K]^T (+bias) ----------------
// block tile 128x128, BK=32, 256 threads = 8 warps, warp tile 64x32,
// mma.m16n8k16.bf16, smem row stride 40 halves (word bank = 20*row + c, conflict-free),
// double-buffered smem (one barrier per K-iter).
__global__ void __launch_bounds__(256, 2)
gemm_bf16(const float* __restrict__ A, const float* __restrict__ Bt,
          const float* __restrict__ bias, float* __restrict__ C,
          int M, int N, int K,
          long long sA, long long sB, long long sC)
{
    __shared__ __nv_bfloat16 As[2][128 * 40];
    __shared__ __nv_bfloat16 Bs[2][128 * 40];

    const int tid  = threadIdx.x;
    const int warp = tid >> 5;
    const int lane = tid & 31;
    const int g = lane >> 2;     // 0..7
    const int c = lane & 3;      // 0..3
    const int wm = warp & 1;     // 64-row slab
    const int wn = warp >> 1;    // 32-col slab

    A  += (size_t)blockIdx.z * sA;
    Bt += (size_t)blockIdx.z * sB;
    C  += (size_t)blockIdx.z * sC;

    const int row0 = blockIdx.y * 128;
    const int col0 = blockIdx.x * 128;

    float acc[4][4][4];
#pragma unroll
    for (int i = 0; i < 4; i++)
#pragma unroll
        for (int j = 0; j < 4; j++)
#pragma unroll
            for (int t = 0; t < 4; t++) acc[i][j][t] = 0.f;

    // loader: 128 rows x 8 float4-cols = 1024 slots, 4 per thread
    int lrow[4], lc4[4];
#pragma unroll
    for (int i = 0; i < 4; i++) { int s = tid + i * 256; lrow[i] = s >> 3; lc4[i] = (s & 7) * 4; }

    float4 pa[4], pb[4];
#pragma unroll
    for (int i = 0; i < 4; i++) {
        pa[i] = *(const float4*)&A[(size_t)(row0 + lrow[i]) * K + lc4[i]];
        pb[i] = *(const float4*)&Bt[(size_t)(col0 + lrow[i]) * K + lc4[i]];
    }

    int p = 0;
    for (int k0 = 0; k0 < K; k0 += 32) {
#pragma unroll
        for (int i = 0; i < 4; i++) {
            *(uint2*)&As[p][lrow[i] * 40 + lc4[i]] =
                make_uint2(pack_bf16(pa[i].x, pa[i].y), pack_bf16(pa[i].z, pa[i].w));
            *(uint2*)&Bs[p][lrow[i] * 40 + lc4[i]] =
                make_uint2(pack_bf16(pb[i].x, pb[i].y), pack_bf16(pb[i].z, pb[i].w));
        }
        __syncthreads();

        if (k0 + 32 < K) {
#pragma unroll
            for (int i = 0; i < 4; i++) {
                pa[i] = *(const float4*)&A[(size_t)(row0 + lrow[i]) * K + k0 + 32 + lc4[i]];
                pb[i] = *(const float4*)&Bt[(size_t)(col0 + lrow[i]) * K + k0 + 32 + lc4[i]];
            }
        }

#pragma unroll
        for (int ks = 0; ks < 2; ks++) {
            const int kk = ks * 16;
            unsigned a[4][4], b[4][2];
#pragma unroll
            for (int i = 0; i < 4; i++) {
                int m = wm * 64 + i * 16 + g;
                a[i][0] = *(const unsigned*)&As[p][m * 40 + kk + 2 * c];
                a[i][1] = *(const unsigned*)&As[p][(m + 8) * 40 + kk + 2 * c];
                a[i][2] = *(const unsigned*)&As[p][m * 40 + kk + 2 * c + 8];
                a[i][3] = *(const unsigned*)&As[p][(m + 8) * 40 + kk + 2 * c + 8];
            }
#pragma unroll
            for (int j = 0; j < 4; j++) {
                int n = wn * 32 + j * 8 + g;
                b[j][0] = *(const unsigned*)&Bs[p][n * 40 + kk + 2 * c];
                b[j][1] = *(const unsigned*)&Bs[p][n * 40 + kk + 2 * c + 8];
            }
#pragma unroll
            for (int i = 0; i < 4; i++)
#pragma unroll
                for (int j = 0; j < 4; j++)
                    mma_bf16(acc[i][j][0], acc[i][j][1], acc[i][j][2], acc[i][j][3],
                             a[i][0], a[i][1], a[i][2], a[i][3], b[j][0], b[j][1]);
        }
        p ^= 1;
    }

    // epilogue: c0:(g,2c) c1:(g,2c+1) c2:(g+8,2c) c3:(g+8,2c+1)
#pragma unroll
    for (int i = 0; i < 4; i++) {
        int r0 = row0 + wm * 64 + i * 16 + g;
#pragma unroll
        for (int j = 0; j < 4; j++) {
            int cc = col0 + wn * 32 + j * 8 + 2 * c;
            float b0 = bias ? bias[cc] : 0.f;
            float b1 = bias ? bias[cc + 1] : 0.f;
            C[(size_t)r0 * N + cc]            = acc[i][j][0] + b0;
            C[(size_t)r0 * N + cc + 1]        = acc[i][j][1] + b1;
            C[(size_t)(r0 + 8) * N + cc]      = acc[i][j][2] + b0;
            C[(size_t)(r0 + 8) * N + cc + 1]  = acc[i][j][3] + b1;
        }
    }
}

// ---------------- column mean over L (two stage) ----------------
__global__ void colmean_part(const float* __restrict__ X, float* __restrict__ part)
{
    int b = blockIdx.x, gg = blockIdx.y, d = threadIdx.x;
    const float* Xb = X + (size_t)b * LLEN * DDIM;
    float s = 0.f;
    int l0 = gg * (LLEN / 16);
    for (int t = 0; t < LLEN / 16; t++) s += Xb[(size_t)(l0 + t) * DDIM + d];
    part[((size_t)b * 16 + gg) * DDIM + d] = s;
}

__global__ void colmean_fin(const float* __restrict__ part, float* __restrict__ sc)
{
    int b = blockIdx.x, d = threadIdx.x;
    float s = 0.f;
    for (int gg = 0; gg < 16; gg++) s += part[((size_t)b * 16 + gg) * DDIM + d];
    sc[b * DDIM + d] = s * (1.0f / LLEN);
}

// ---------------- exact scores: sc[b,j] = dot(meanX[b], W[j]) + bias[j] ----------------
__global__ void score_kernel(const float* __restrict__ meanX, const float* __restrict__ W,
                             const float* __restrict__ bias, float* __restrict__ out)
{
    __shared__ float mx[DDIM];
    int b = blockIdx.y;
    int tid = threadIdx.x, warp = tid >> 5, lane = tid & 31;
    for (int e = tid; e < DDIM; e += 256) mx[e] = meanX[b * DDIM + e];
    __syncthreads();
    int j = blockIdx.x * 8 + warp;
    const float* Wr = W + (size_t)j * DDIM;
    float s = 0.f;
    for (int kk = lane; kk < DDIM; kk += 32) s += mx[kk] * Wr[kk];
    for (int o = 16; o > 0; o >>= 1) s += __shfl_xor_sync(0xffffffffu, s, o);
    if (lane == 0) out[b * DDIM + j] = s + bias[j];
}

// ---------------- Bsum_j = sum_k |s_j - s_k| ----------------
__global__ void bsum_kernel(const float* __restrict__ sc, float* __restrict__ bs)
{
    __shared__ float ss[1024];
    int b = blockIdx.x, j = threadIdx.x;
    float sj = sc[b * 1024 + j];
    ss[j] = sj;
    __syncthreads();
    float a = 0.f;
    for (int kk = 0; kk < 1024; kk++) a += fabsf(sj - ss[kk]);
    bs[b * 1024 + j] = a;
}

// ---------------- P[b,i,j] = softmax_j( s_j*(n-1-2i) - Bsum_j ) ----------------
__global__ void sortP_kernel(const float* __restrict__ sc, const float* __restrict__ bs,
                             float* __restrict__ P)
{
    const int n = 1024;
    int i = blockIdx.x, b = blockIdx.y;
    int tid = threadIdx.x;
    const float* s  = sc + b * n;
    const float* Bv = bs + b * n;
    float scal = (float)(n - 1 - 2 * i);

    float v[4]; float mx = -1e30f;
#pragma unroll
    for (int t = 0; t < 4; t++) {
        int j = tid + t * 256;
        float x = s[j] * scal - Bv[j];
        v[t] = x; mx = fmaxf(mx, x);
    }
    __shared__ float sm[8];
    __shared__ float tot;
    for (int o = 16; o > 0; o >>= 1) mx = fmaxf(mx, __shfl_xor_sync(0xffffffffu, mx, o));
    if ((tid & 31) == 0) sm[tid >> 5] = mx;
    __syncthreads();
    if (tid == 0) { float t2 = sm[0]; for (int w = 1; w < 8; w++) t2 = fmaxf(t2, sm[w]); tot = t2; }
    __syncthreads();
    mx = tot;
    float sum = 0.f;
#pragma unroll
    for (int t = 0; t < 4; t++) { float e = expf(v[t] - mx); v[t] = e; sum += e; }
    __syncthreads();
    for (int o = 16; o > 0; o >>= 1) sum += __shfl_xor_sync(0xffffffffu, sum, o);
    if ((tid & 31) == 0) sm[tid >> 5] = sum;
    __syncthreads();
    if (tid == 0) { float t2 = 0.f; for (int w = 0; w < 8; w++) t2 += sm[w]; tot = t2; }
    __syncthreads();
    float inv = 1.0f / tot;
    float* Pr = P + ((size_t)b * n + i) * n;
#pragma unroll
    for (int t = 0; t < 4; t++) Pr[tid + t * 256] = v[t] * inv;
}

// ---------------- Euler pointwise (in-place, float2 pairs) ----------------
__global__ void euler_kernel(float* __restrict__ X, const float* __restrict__ delta,
                             const float* __restrict__ b_euler, const float* __restrict__ log_scale,
                             int add_b)
{
    int idx = blockIdx.x * blockDim.x + threadIdx.x;
    int i = idx & 511;
    float2 rp = ((float2*)X)[idx];
    float r = rp.x, p = rp.y;
    float lam = sqrtf(r * r + p * p + 1e-6f);
    float th = atan2f(p / lam, r / lam) * delta[i];
    if (add_b) th += b_euler[i];
    float ls = fminf(fmaxf(log_scale[i], -5.f), 5.f);
    lam = lam * expf(ls);
    ((float2*)X)[idx] = make_float2(lam * cosf(th), lam * sinf(th));
}

// ---------------- flash attention (tf32 tensor core, online softmax) ----------------
// grid (L/128, B*H), block 256 = 8 warps; warp owns 16 q rows; K/V tile = 64.
__global__ void __launch_bounds__(256, 1)
flash_tf32(const float* __restrict__ Q, const float* __restrict__ K,
           const float* __restrict__ V, float* __restrict__ O)
{
    __shared__ unsigned ks[64 * 68];   // [key][d]  stride 68: banks 4g+c, conflict-free
    __shared__ unsigned vs[64 * 72];   // [key][d]  stride 72: banks 8c+g, conflict-free

    const int tid  = threadIdx.x;
    const int warp = tid >> 5;
    const int lane = tid & 31;
    const int g = lane >> 2;
    const int c = lane & 3;
    const int bh = blockIdx.y;
    const int b = bh >> 4, h = bh & 15;
    const int q0 = blockIdx.x * 128 + warp * 16;

    const float* Qb = Q + (size_t)b * LLEN * DDIM + h * DHEAD;
    const float* Kb = K + (size_t)b * LLEN * DDIM + h * DHEAD;
    const float* Vb = V + (size_t)b * LLEN * DDIM + h * DHEAD;
    float* Ob       = O + (size_t)b * LLEN * DDIM + h * DHEAD;

    // Q fragments in registers (scaled by 1/sqrt(64)), 8 k-chunks of 8
    unsigned qf[8][4];
#pragma unroll
    for (int kc = 0; kc < 8; kc++) {
        qf[kc][0] = f2tf32(Qb[(size_t)(q0 + g)     * DDIM + kc * 8 + c]     * 0.125f);
        qf[kc][1] = f2tf32(Qb[(size_t)(q0 + g + 8) * DDIM + kc * 8 + c]     * 0.125f);
        qf[kc][2] = f2tf32(Qb[(size_t)(q0 + g)     * DDIM + kc * 8 + c + 4] * 0.125f);
        qf[kc][3] = f2tf32(Qb[(size_t)(q0 + g + 8) * DDIM + kc * 8 + c + 4] * 0.125f);
    }

    float o[8][4];
#pragma unroll
    for (int j = 0; j < 8; j++)
#pragma unroll
        for (int t = 0; t < 4; t++) o[j][t] = 0.f;
    float m0 = -1e30f, m8 = -1e30f, l0 = 0.f, l8 = 0.f;

    for (int k0 = 0; k0 < LLEN; k0 += 64) {
        __syncthreads();
        // load K,V tile: 64 rows x 16 float4-cols = 1024 slots, 4 per thread
#pragma unroll
        for (int i = 0; i < 4; i++) {
            int slot = tid + i * 256;          // 0..1023
            int row = slot >> 4, c4 = (slot & 15) * 4;
            float4 kk4 = *(const float4*)&Kb[(size_t)(k0 + row) * DDIM + c4];
            float4 vv4 = *(const float4*)&Vb[(size_t)(k0 + row) * DDIM + c4];
            *(uint4*)&ks[row * 68 + c4] = make_uint4(f2tf32(kk4.x), f2tf32(kk4.y), f2tf32(kk4.z), f2tf32(kk4.w));
            *(uint4*)&vs[row * 72 + c4] = make_uint4(f2tf32(vv4.x), f2tf32(vv4.y), f2tf32(vv4.z), f2tf32(vv4.w));
        }
        __syncthreads();

        // S = Q K^T  (16x64 per warp)
        float s[8][4];
#pragma unroll
        for (int j = 0; j < 8; j++)
#pragma unroll
            for (int t = 0; t < 4; t++) s[j][t] = 0.f;
#pragma unroll
        for (int kc = 0; kc < 8; kc++) {
#pragma unroll
            for (int j = 0; j < 8; j++) {
                unsigned b0 = ks[(j * 8 + g) * 68 + kc * 8 + c];
                unsigned b1 = ks[(j * 8 + g) * 68 + kc * 8 + c + 4];
                mma_tf32(s[j][0], s[j][1], s[j][2], s[j][3],
                         qf[kc][0], qf[kc][1], qf[kc][2], qf[kc][3], b0, b1);
            }
        }

        // online softmax (rows g and g+8, reductions within c-quad)
        float tm0 = -1e30f, tm8 = -1e30f;
#pragma unroll
        for (int j = 0; j < 8; j++) {
            tm0 = fmaxf(tm0, fmaxf(s[j][0], s[j][1]));
            tm8 = fmaxf(tm8, fmaxf(s[j][2], s[j][3]));
        }
        tm0 = fmaxf(tm0, __shfl_xor_sync(0xffffffffu, tm0, 1));
        tm0 = fmaxf(tm0, __shfl_xor_sync(0xffffffffu, tm0, 2));
        tm8 = fmaxf(tm8, __shfl_xor_sync(0xffffffffu, tm8, 1));
        tm8 = fmaxf(tm8, __shfl_xor_sync(0xffffffffu, tm8, 2));

        float mn0 = fmaxf(m0, tm0), mn8 = fmaxf(m8, tm8);
        float sc0 = __expf(m0 - mn0), sc8 = __expf(m8 - mn8);
        m0 = mn0; m8 = mn8;

        float rs0 = 0.f, rs8 = 0.f;
#pragma unroll
        for (int j = 0; j < 8; j++) {
            s[j][0] = __expf(s[j][0] - mn0);
            s[j][1] = __expf(s[j][1] - mn0);
            s[j][2] = __expf(s[j][2] - mn8);
            s[j][3] = __expf(s[j][3] - mn8);
            rs0 += s[j][0] + s[j][1];
            rs8 += s[j][2] + s[j][3];
        }
        rs0 += __shfl_xor_sync(0xffffffffu, rs0, 1);
        rs0 += __shfl_xor_sync(0xffffffffu, rs0, 2);
        rs8 += __shfl_xor_sync(0xffffffffu, rs8, 1);
        rs8 += __shfl_xor_sync(0xffffffffu, rs8, 2);
        l0 = l0 * sc0 + rs0;
        l8 = l8 * sc8 + rs8;

#pragma unroll
        for (int j = 0; j < 8; j++) {
            o[j][0] *= sc0; o[j][1] *= sc0;
            o[j][2] *= sc8; o[j][3] *= sc8;
        }

        // O += P V : relayout P frags (C-layout -> A-layout) via quad shuffles
        const int src0 = (lane & ~3) | (c >> 1);
        const bool odd = (c & 1);
#pragma unroll
        for (int kc = 0; kc < 8; kc++) {
            float u0 = __shfl_sync(0xffffffffu, s[kc][0], src0);
            float u1 = __shfl_sync(0xffffffffu, s[kc][1], src0);
            float w0 = __shfl_sync(0xffffffffu, s[kc][0], src0 + 2);
            float w1 = __shfl_sync(0xffffffffu, s[kc][1], src0 + 2);
            float x0 = __shfl_sync(0xffffffffu, s[kc][2], src0);
            float x1 = __shfl_sync(0xffffffffu, s[kc][3], src0);
            float y0 = __shfl_sync(0xffffffffu, s[kc][2], src0 + 2);
            float y1 = __shfl_sync(0xffffffffu, s[kc][3], src0 + 2);
            unsigned a0 = f2tf32(odd ? u1 : u0);
            unsigned a2 = f2tf32(odd ? w1 : w0);
            unsigned a1 = f2tf32(odd ? x1 : x0);
            unsigned a3 = f2tf32(odd ? y1 : y0);
#pragma unroll
            for (int j = 0; j < 8; j++) {
                unsigned b0 = vs[(kc * 8 + c)     * 72 + j * 8 + g];
                unsigned b1 = vs[(kc * 8 + c + 4) * 72 + j * 8 + g];
                mma_tf32(o[j][0], o[j][1], o[j][2], o[j][3], a0, a1, a2, a3, b0, b1);
            }
        }
    }

    float inv0 = 1.0f / l0, inv8 = 1.0f / l8;
#pragma unroll
    for (int j = 0; j < 8; j++) {
        int cc = j * 8 + 2 * c;
        *(float2*)&Ob[(size_t)(q0 + g)     * DDIM + cc] = make_float2(o[j][0] * inv0, o[j][1] * inv0);
        *(float2*)&Ob[(size_t)(q0 + g + 8) * DDIM + cc] = make_float2(o[j][2] * inv8, o[j][3] * inv8);
    }
}

// ---------------- residual + LayerNorm ----------------
__global__ void ln_kernel(const float* __restrict__ hid, const float* __restrict__ inp,
                          const float* __restrict__ gamma, const float* __restrict__ beta,
                          float* __restrict__ out)
{
    size_t row = blockIdx.x;
    int tid = threadIdx.x;
    float x[4];
    float s = 0.f;
#pragma unroll
    for (int t = 0; t < 4; t++) {
        int d = tid + t * 256;
        x[t] = hid[row * DDIM + d] + inp[row * DDIM + d];
        s += x[t];
    }
    __shared__ float sm[8];
    __shared__ float tot;
    for (int o = 16; o > 0; o >>= 1) s += __shfl_xor_sync(0xffffffffu, s, o);
    if ((tid & 31) == 0) sm[tid >> 5] = s;
    __syncthreads();
    if (tid == 0) { float t2 = 0.f; for (int w = 0; w < 8; w++) t2 += sm[w]; tot = t2; }
    __syncthreads();
    float mu = tot * (1.0f / DDIM);
    float vsum = 0.f;
#pragma unroll
    for (int t = 0; t < 4; t++) { float dd = x[t] - mu; vsum += dd * dd; }
    __syncthreads();
    for (int o = 16; o > 0; o >>= 1) vsum += __shfl_xor_sync(0xffffffffu, vsum, o);
    if ((tid & 31) == 0) sm[tid >> 5] = vsum;
    __syncthreads();
    if (tid == 0) { float t2 = 0.f; for (int w = 0; w < 8; w++) t2 += sm[w]; tot = t2; }
    __syncthreads();
    float var = tot * (1.0f / DDIM);
    float inv = 1.0f / sqrtf(var + 1e-12f);
#pragma unroll
    for (int t = 0; t < 4; t++) {
        int d = tid + t * 256;
        out[row * DDIM + d] = (x[t] - mu) * inv * gamma[d] + beta[d];
    }
}

// ---------------- driver ----------------
extern "C" void kernel_launch(void* const* d_in, const int* in_sizes, int n_in,
                              void* d_out, int out_size)
{
    const float* X   = (const float*)d_in[0];
    const float* Wq  = (const float*)d_in[1];
    const float* bq  = (const float*)d_in[2];
    const float* Wk  = (const float*)d_in[3];
    const float* bk  = (const float*)d_in[4];
    const float* Wv  = (const float*)d_in[5];
    const float* bv  = (const float*)d_in[6];
    const float* Wd  = (const float*)d_in[7];
    const float* bd  = (const float*)d_in[8];
    const float* gamma     = (const float*)d_in[9];
    const float* beta      = (const float*)d_in[10];
    const float* delta     = (const float*)d_in[11];
    const float* b_euler   = (const float*)d_in[12];
    const float* log_scale = (const float*)d_in[13];
    float* out = (float*)d_out;

    float *q, *k, *v, *q2, *k2, *ctx, *hid, *Pq, *Pk, *scq, *sck, *pX, *meanX, *bsq, *bsk;
    { void* p;
      cudaGetSymbolAddress(&p, g_q);     q     = (float*)p;
      cudaGetSymbolAddress(&p, g_k);     k     = (float*)p;
      cudaGetSymbolAddress(&p, g_v);     v     = (float*)p;
      cudaGetSymbolAddress(&p, g_q2);    q2    = (float*)p;
      cudaGetSymbolAddress(&p, g_k2);    k2    = (float*)p;
      cudaGetSymbolAddress(&p, g_ctx);   ctx   = (float*)p;
      cudaGetSymbolAddress(&p, g_hid);   hid   = (float*)p;
      cudaGetSymbolAddress(&p, g_Pq);    Pq    = (float*)p;
      cudaGetSymbolAddress(&p, g_Pk);    Pk    = (float*)p;
      cudaGetSymbolAddress(&p, g_scq);   scq   = (float*)p;
      cudaGetSymbolAddress(&p, g_sck);   sck   = (float*)p;
      cudaGetSymbolAddress(&p, g_partX); pX    = (float*)p;
      cudaGetSymbolAddress(&p, g_meanX); meanX = (float*)p;
      cudaGetSymbolAddress(&p, g_bsq);   bsq   = (float*)p;
      cudaGetSymbolAddress(&p, g_bsk);   bsk   = (float*)p;
    }

    const int M = BB * LLEN;   // 4096

    // exact scores path (fp32)
    colmean_part<<<dim3(BB, 16), 1024>>>(X, pX);
    colmean_fin<<<BB, 1024>>>(pX, meanX);
    score_kernel<<<dim3(DDIM / 8, BB), 256>>>(meanX, Wq, bq, scq);
    score_kernel<<<dim3(DDIM / 8, BB), 256>>>(meanX, Wk, bk, sck);

    // projections (bf16 tensor core)
    gemm_bf16<<<dim3(DDIM/128, M/128, 1), 256>>>(X, Wq, bq, q, M, DDIM, DDIM, 0, 0, 0);
    gemm_bf16<<<dim3(DDIM/128, M/128, 1), 256>>>(X, Wk, bk, k, M, DDIM, DDIM, 0, 0, 0);
    gemm_bf16<<<dim3(DDIM/128, M/128, 1), 256>>>(X, Wv, bv, v, M, DDIM, DDIM, 0, 0, 0);

    // neural sort permutation matrices (fp32-exact scores)
    bsum_kernel<<<BB, 1024>>>(scq, bsq);
    bsum_kernel<<<BB, 1024>>>(sck, bsk);
    sortP_kernel<<<dim3(DDIM, BB), 256>>>(scq, bsq, Pq);
    sortP_kernel<<<dim3(DDIM, BB), 256>>>(sck, bsk, Pk);

    // v_sorted = x @ P^T  (batched bf16)
    gemm_bf16<<<dim3(DDIM/128, LLEN/128, BB), 256>>>(q, Pq, nullptr, q2, LLEN, DDIM, DDIM,
                                                     (long long)LLEN*DDIM, (long long)DDIM*DDIM, (long long)LLEN*DDIM);
    gemm_bf16<<<dim3(DDIM/128, LLEN/128, BB), 256>>>(k, Pk, nullptr, k2, LLEN, DDIM, DDIM,
                                                     (long long)LLEN*DDIM, (long long)DDIM*DDIM, (long long)LLEN*DDIM);

    // euler pointwise (in place)
    euler_kernel<<<(BB*LLEN*(DDIM/2))/256, 256>>>(q2, delta, b_euler, log_scale, 1);
    euler_kernel<<<(BB*LLEN*(DDIM/2))/256, 256>>>(k2, delta, b_euler, log_scale, 0);

    // attention (tf32 tensor core flash)
    flash_tf32<<<dim3(LLEN/128, BB*NHEAD), 256>>>(q2, k2, v, ctx);

    // output projection (bf16)
    gemm_bf16<<<dim3(DDIM/128, M/128, 1), 256>>>(ctx, Wd, bd, hid, M, DDIM, DDIM, 0, 0, 0);

    // residual + layernorm
    ln_kernel<<<M, 256>>>(hid, X, gamma, beta, out);
}

// round 11
// speedup vs baseline: 5.1762x; 1.0522x over previous
#include <cuda_runtime.h>
#include <cuda_bf16.h>
#include <math.h>

#define BB 2
#define LLEN 2048
#define DDIM 1024
#define NHEAD 16
#define DHEAD 64

// ---------------- scratch (device globals; no allocations allowed) ----------------
__device__ float g_q[BB*LLEN*DDIM];
__device__ float g_k[BB*LLEN*DDIM];
__device__ float g_v[BB*LLEN*DDIM];
__device__ float g_q2[BB*LLEN*DDIM];
__device__ float g_k2[BB*LLEN*DDIM];
__device__ float g_ctx[BB*LLEN*DDIM];
__device__ float g_hid[BB*LLEN*DDIM];
__device__ float g_Pq[BB*DDIM*DDIM];
__device__ float g_Pk[BB*DDIM*DDIM];
__device__ float g_scq[BB*DDIM];
__device__ float g_sck[BB*DDIM];
__device__ float g_partX[BB*16*DDIM];
__device__ float g_meanX[BB*DDIM];
__device__ float g_bsq[BB*DDIM];
__device__ float g_bsk[BB*DDIM];

// ---------------- helpers ----------------
__device__ __forceinline__ unsigned f2tf32(float f) {
    unsigned r;
    asm("cvt.rna.tf32.f32 %0, %1;" : "=r"(r) : "f"(f));
    return r;
}

__device__ __forceinline__ void mma_tf32(float& c0, float& c1, float& c2, float& c3,
                                         unsigned a0, unsigned a1, unsigned a2, unsigned a3,
                                         unsigned b0, unsigned b1)
{
    asm volatile("mma.sync.aligned.m16n8k8.row.col.f32.tf32.tf32.f32 "
                 "{%0,%1,%2,%3}, {%4,%5,%6,%7}, {%8,%9}, {%0,%1,%2,%3};"
                 : "+f"(c0), "+f"(c1), "+f"(c2), "+f"(c3)
                 : "r"(a0), "r"(a1), "r"(a2), "r"(a3), "r"(b0), "r"(b1));
}

__device__ __forceinline__ void mma_bf16(float& c0, float& c1, float& c2, float& c3,
                                         unsigned a0, unsigned a1, unsigned a2, unsigned a3,
                                         unsigned b0, unsigned b1)
{
    asm volatile("mma.sync.aligned.m16n8k16.row.col.f32.bf16.bf16.f32 "
                 "{%0,%1,%2,%3}, {%4,%5,%6,%7}, {%8,%9}, {%0,%1,%2,%3};"
                 : "+f"(c0), "+f"(c1), "+f"(c2), "+f"(c3)
                 : "r"(a0), "r"(a1), "r"(a2), "r"(a3), "r"(b0), "r"(b1));
}

__device__ __forceinline__ unsigned pack_bf16(float lo, float hi) {
    __nv_bfloat162 t = __floats2bfloat162_rn(lo, hi);
    return *(unsigned*)&t;
}

__device__ __forceinline__ void ldsm_x4(unsigned& r0, unsigned& r1, unsigned& r2, unsigned& r3,
                                        unsigned addr)
{
    asm volatile("ldmatrix.sync.aligned.m8n8.x4.shared.b16 {%0,%1,%2,%3}, [%4];"
                 : "=r"(r0), "=r"(r1), "=r"(r2), "=r"(r3) : "r"(addr));
}

__device__ __forceinline__ void ldsm_x2(unsigned& r0, unsigned& r1, unsigned addr)
{
    asm volatile("ldmatrix.sync.aligned.m8n8.x2.shared.b16 {%0,%1}, [%2];"
                 : "=r"(r0), "=r"(r1) : "r"(addr));
}

// ---------------- BF16 GEMM: C[M,N] = A[M,K] @ Bt[N,K]^T ----------------
// block 128x128, BK=32, 8 warps, warp tile 64x32, m16n8k16, ldmatrix fragment loads,
// smem row stride 40 halves (LDSM phase rows at words 20r mod 32 — all distinct),
// double-buffered. Epilogue: mode 0 = +bias store; mode 1/2 = fused Euler (1 adds b_euler).
__global__ void __launch_bounds__(256, 2)
gemm_bf16(const float* __restrict__ A, const float* __restrict__ Bt,
          const float* __restrict__ bias, float* __restrict__ C,
          int M, int N, int K,
          long long sA, long long sB, long long sC,
          int mode,
          const float* __restrict__ delta, const float* __restrict__ b_euler,
          const float* __restrict__ log_scale)
{
    __shared__ __nv_bfloat16 As[2][128 * 40];
    __shared__ __nv_bfloat16 Bs[2][128 * 40];

    const int tid  = threadIdx.x;
    const int warp = tid >> 5;
    const int lane = tid & 31;
    const int g = lane >> 2;
    const int c = lane & 3;
    const int wm = warp & 1;
    const int wn = warp >> 1;

    A  += (size_t)blockIdx.z * sA;
    Bt += (size_t)blockIdx.z * sB;
    C  += (size_t)blockIdx.z * sC;

    const int row0 = blockIdx.y * 128;
    const int col0 = blockIdx.x * 128;

    // ldmatrix per-thread base addresses (bytes; row stride 80B)
    const unsigned aBase = (unsigned)__cvta_generic_to_shared(&As[0][0])
                         + ((wm * 64 + (lane & 15)) * 40 + (lane >> 4) * 8) * 2;
    const unsigned bBase = (unsigned)__cvta_generic_to_shared(&Bs[0][0])
                         + ((wn * 32 + (lane & 7)) * 40 + ((lane >> 3) & 1) * 8) * 2;
    const unsigned bufStride = 128 * 40 * 2;   // bytes between buffer 0 and 1

    float acc[4][4][4];
#pragma unroll
    for (int i = 0; i < 4; i++)
#pragma unroll
        for (int j = 0; j < 4; j++)
#pragma unroll
            for (int t = 0; t < 4; t++) acc[i][j][t] = 0.f;

    int lrow[4], lc4[4];
#pragma unroll
    for (int i = 0; i < 4; i++) { int s = tid + i * 256; lrow[i] = s >> 3; lc4[i] = (s & 7) * 4; }

    float4 pa[4], pb[4];
#pragma unroll
    for (int i = 0; i < 4; i++) {
        pa[i] = *(const float4*)&A[(size_t)(row0 + lrow[i]) * K + lc4[i]];
        pb[i] = *(const float4*)&Bt[(size_t)(col0 + lrow[i]) * K + lc4[i]];
    }

    int p = 0;
    for (int k0 = 0; k0 < K; k0 += 32) {
#pragma unroll
        for (int i = 0; i < 4; i++) {
            *(uint2*)&As[p][lrow[i] * 40 + lc4[i]] =
                make_uint2(pack_bf16(pa[i].x, pa[i].y), pack_bf16(pa[i].z, pa[i].w));
            *(uint2*)&Bs[p][lrow[i] * 40 + lc4[i]] =
                make_uint2(pack_bf16(pb[i].x, pb[i].y), pack_bf16(pb[i].z, pb[i].w));
        }
        __syncthreads();

        if (k0 + 32 < K) {
#pragma unroll
            for (int i = 0; i < 4; i++) {
                pa[i] = *(const float4*)&A[(size_t)(row0 + lrow[i]) * K + k0 + 32 + lc4[i]];
                pb[i] = *(const float4*)&Bt[(size_t)(col0 + lrow[i]) * K + k0 + 32 + lc4[i]];
            }
        }

        const unsigned aB = aBase + p * bufStride;
        const unsigned bB = bBase + p * bufStride;
#pragma unroll
        for (int ks = 0; ks < 2; ks++) {
            unsigned a[4][4], b[4][2];
#pragma unroll
            for (int i = 0; i < 4; i++)
                ldsm_x4(a[i][0], a[i][1], a[i][2], a[i][3], aB + i * 16 * 80 + ks * 32);
#pragma unroll
            for (int j = 0; j < 4; j++)
                ldsm_x2(b[j][0], b[j][1], bB + j * 8 * 80 + ks * 32);
#pragma unroll
            for (int i = 0; i < 4; i++)
#pragma unroll
                for (int j = 0; j < 4; j++)
                    mma_bf16(acc[i][j][0], acc[i][j][1], acc[i][j][2], acc[i][j][3],
                             a[i][0], a[i][1], a[i][2], a[i][3], b[j][0], b[j][1]);
        }
        p ^= 1;
    }

    if (mode == 0) {
#pragma unroll
        for (int i = 0; i < 4; i++) {
            int r0 = row0 + wm * 64 + i * 16 + g;
#pragma unroll
            for (int j = 0; j < 4; j++) {
                int cc = col0 + wn * 32 + j * 8 + 2 * c;
                float b0 = bias ? bias[cc] : 0.f;
                float b1 = bias ? bias[cc + 1] : 0.f;
                *(float2*)&C[(size_t)r0 * N + cc]       = make_float2(acc[i][j][0] + b0, acc[i][j][1] + b1);
                *(float2*)&C[(size_t)(r0 + 8) * N + cc] = make_float2(acc[i][j][2] + b0, acc[i][j][3] + b1);
            }
        }
    } else {
        // fused Euler: acc pair (t0,t1) = (r,p) at cols (cc, cc+1), pair index cc/2
#pragma unroll
        for (int j = 0; j < 4; j++) {
            int cc = col0 + wn * 32 + j * 8 + 2 * c;
            int pi = cc >> 1;
            float dlt = delta[pi];
            float bev = (mode == 1) ? b_euler[pi] : 0.f;
            float lsv = fminf(fmaxf(log_scale[pi], -5.f), 5.f);
            float es  = expf(lsv);
#pragma unroll
            for (int i = 0; i < 4; i++) {
                int r0 = row0 + wm * 64 + i * 16 + g;
#pragma unroll
                for (int half = 0; half < 2; half++) {
                    float rr = acc[i][j][half * 2 + 0];
                    float pp = acc[i][j][half * 2 + 1];
                    float lam = sqrtf(rr * rr + pp * pp + 1e-6f);
                    float th  = atan2f(pp / lam, rr / lam) * dlt + bev;
                    float lo  = lam * es;
                    *(float2*)&C[(size_t)(r0 + half * 8) * N + cc] =
                        make_float2(lo * cosf(th), lo * sinf(th));
                }
            }
        }
    }
}

// ---------------- column mean over L (two stage) ----------------
__global__ void colmean_part(const float* __restrict__ X, float* __restrict__ part)
{
    int b = blockIdx.x, gg = blockIdx.y, d = threadIdx.x;
    const float* Xb = X + (size_t)b * LLEN * DDIM;
    float s = 0.f;
    int l0 = gg * (LLEN / 16);
    for (int t = 0; t < LLEN / 16; t++) s += Xb[(size_t)(l0 + t) * DDIM + d];
    part[((size_t)b * 16 + gg) * DDIM + d] = s;
}

__global__ void colmean_fin(const float* __restrict__ part, float* __restrict__ sc)
{
    int b = blockIdx.x, d = threadIdx.x;
    float s = 0.f;
    for (int gg = 0; gg < 16; gg++) s += part[((size_t)b * 16 + gg) * DDIM + d];
    sc[b * DDIM + d] = s * (1.0f / LLEN);
}

// ---------------- exact scores: z selects (Wq,bq,scq) vs (Wk,bk,sck) ----------------
__global__ void score_kernel(const float* __restrict__ meanX,
                             const float* __restrict__ Wq, const float* __restrict__ bq,
                             const float* __restrict__ Wk, const float* __restrict__ bk,
                             float* __restrict__ outq, float* __restrict__ outk)
{
    __shared__ float mx[DDIM];
    int b = blockIdx.y;
    const float* W    = blockIdx.z ? Wk : Wq;
    const float* bias = blockIdx.z ? bk : bq;
    float* out        = blockIdx.z ? outk : outq;
    int tid = threadIdx.x, warp = tid >> 5, lane = tid & 31;
    for (int e = tid; e < DDIM; e += 256) mx[e] = meanX[b * DDIM + e];
    __syncthreads();
    int j = blockIdx.x * 8 + warp;
    const float* Wr = W + (size_t)j * DDIM;
    float s = 0.f;
    for (int kk = lane; kk < DDIM; kk += 32) s += mx[kk] * Wr[kk];
    for (int o = 16; o > 0; o >>= 1) s += __shfl_xor_sync(0xffffffffu, s, o);
    if (lane == 0) out[b * DDIM + j] = s + bias[j];
}

// ---------------- Bsum_j = sum_k |s_j - s_k|  (z selects q/k) ----------------
__global__ void bsum_kernel(const float* __restrict__ scq, const float* __restrict__ sck,
                            float* __restrict__ bsq, float* __restrict__ bsk)
{
    __shared__ float ss[1024];
    const float* sc = blockIdx.y ? sck : scq;
    float* bs       = blockIdx.y ? bsk : bsq;
    int b = blockIdx.x, j = threadIdx.x;
    float sj = sc[b * 1024 + j];
    ss[j] = sj;
    __syncthreads();
    float a = 0.f;
    for (int kk = 0; kk < 1024; kk++) a += fabsf(sj - ss[kk]);
    bs[b * 1024 + j] = a;
}

// ---------------- P[b,i,j] = softmax_j( s_j*(n-1-2i) - Bsum_j )  (z selects q/k) ----------------
__global__ void sortP_kernel(const float* __restrict__ scq, const float* __restrict__ bsq,
                             const float* __restrict__ sck, const float* __restrict__ bsk,
                             float* __restrict__ Pq, float* __restrict__ Pk)
{
    const int n = 1024;
    int i = blockIdx.x, b = blockIdx.y;
    const float* s  = (blockIdx.z ? sck : scq) + b * n;
    const float* Bv = (blockIdx.z ? bsk : bsq) + b * n;
    float* P        =  blockIdx.z ? Pk  : Pq;
    int tid = threadIdx.x;
    float scal = (float)(n - 1 - 2 * i);

    float v[4]; float mx = -1e30f;
#pragma unroll
    for (int t = 0; t < 4; t++) {
        int j = tid + t * 256;
        float x = s[j] * scal - Bv[j];
        v[t] = x; mx = fmaxf(mx, x);
    }
    __shared__ float sm[8];
    __shared__ float tot;
    for (int o = 16; o > 0; o >>= 1) mx = fmaxf(mx, __shfl_xor_sync(0xffffffffu, mx, o));
    if ((tid & 31) == 0) sm[tid >> 5] = mx;
    __syncthreads();
    if (tid == 0) { float t2 = sm[0]; for (int w = 1; w < 8; w++) t2 = fmaxf(t2, sm[w]); tot = t2; }
    __syncthreads();
    mx = tot;
    float sum = 0.f;
#pragma unroll
    for (int t = 0; t < 4; t++) { float e = expf(v[t] - mx); v[t] = e; sum += e; }
    __syncthreads();
    for (int o = 16; o > 0; o >>= 1) sum += __shfl_xor_sync(0xffffffffu, sum, o);
    if ((tid & 31) == 0) sm[tid >> 5] = sum;
    __syncthreads();
    if (tid == 0) { float t2 = 0.f; for (int w = 0; w < 8; w++) t2 += sm[w]; tot = t2; }
    __syncthreads();
    float inv = 1.0f / tot;
    float* Pr = P + ((size_t)b * n + i) * n;
#pragma unroll
    for (int t = 0; t < 4; t++) Pr[tid + t * 256] = v[t] * inv;
}

// ---------------- flash attention (tf32 tensor core, online softmax) ----------------
__global__ void __launch_bounds__(256, 1)
flash_tf32(const float* __restrict__ Q, const float* __restrict__ K,
           const float* __restrict__ V, float* __restrict__ O)
{
    __shared__ unsigned ks[64 * 68];
    __shared__ unsigned vs[64 * 72];

    const int tid  = threadIdx.x;
    const int warp = tid >> 5;
    const int lane = tid & 31;
    const int g = lane >> 2;
    const int c = lane & 3;
    const int bh = blockIdx.y;
    const int b = bh >> 4, h = bh & 15;
    const int q0 = blockIdx.x * 128 + warp * 16;

    const float* Qb = Q + (size_t)b * LLEN * DDIM + h * DHEAD;
    const float* Kb = K + (size_t)b * LLEN * DDIM + h * DHEAD;
    const float* Vb = V + (size_t)b * LLEN * DDIM + h * DHEAD;
    float* Ob       = O + (size_t)b * LLEN * DDIM + h * DHEAD;

    unsigned qf[8][4];
#pragma unroll
    for (int kc = 0; kc < 8; kc++) {
        qf[kc][0] = f2tf32(Qb[(size_t)(q0 + g)     * DDIM + kc * 8 + c]     * 0.125f);
        qf[kc][1] = f2tf32(Qb[(size_t)(q0 + g + 8) * DDIM + kc * 8 + c]     * 0.125f);
        qf[kc][2] = f2tf32(Qb[(size_t)(q0 + g)     * DDIM + kc * 8 + c + 4] * 0.125f);
        qf[kc][3] = f2tf32(Qb[(size_t)(q0 + g + 8) * DDIM + kc * 8 + c + 4] * 0.125f);
    }

    float o[8][4];
#pragma unroll
    for (int j = 0; j < 8; j++)
#pragma unroll
        for (int t = 0; t < 4; t++) o[j][t] = 0.f;
    float m0 = -1e30f, m8 = -1e30f, l0 = 0.f, l8 = 0.f;

    for (int k0 = 0; k0 < LLEN; k0 += 64) {
        __syncthreads();
#pragma unroll
        for (int i = 0; i < 4; i++) {
            int slot = tid + i * 256;
            int row = slot >> 4, c4 = (slot & 15) * 4;
            float4 kk4 = *(const float4*)&Kb[(size_t)(k0 + row) * DDIM + c4];
            float4 vv4 = *(const float4*)&Vb[(size_t)(k0 + row) * DDIM + c4];
            *(uint4*)&ks[row * 68 + c4] = make_uint4(f2tf32(kk4.x), f2tf32(kk4.y), f2tf32(kk4.z), f2tf32(kk4.w));
            *(uint4*)&vs[row * 72 + c4] = make_uint4(f2tf32(vv4.x), f2tf32(vv4.y), f2tf32(vv4.z), f2tf32(vv4.w));
        }
        __syncthreads();

        float s[8][4];
#pragma unroll
        for (int j = 0; j < 8; j++)
#pragma unroll
            for (int t = 0; t < 4; t++) s[j][t] = 0.f;
#pragma unroll
        for (int kc = 0; kc < 8; kc++) {
#pragma unroll
            for (int j = 0; j < 8; j++) {
                unsigned b0 = ks[(j * 8 + g) * 68 + kc * 8 + c];
                unsigned b1 = ks[(j * 8 + g) * 68 + kc * 8 + c + 4];
                mma_tf32(s[j][0], s[j][1], s[j][2], s[j][3],
                         qf[kc][0], qf[kc][1], qf[kc][2], qf[kc][3], b0, b1);
            }
        }

        float tm0 = -1e30f, tm8 = -1e30f;
#pragma unroll
        for (int j = 0; j < 8; j++) {
            tm0 = fmaxf(tm0, fmaxf(s[j][0], s[j][1]));
            tm8 = fmaxf(tm8, fmaxf(s[j][2], s[j][3]));
        }
        tm0 = fmaxf(tm0, __shfl_xor_sync(0xffffffffu, tm0, 1));
        tm0 = fmaxf(tm0, __shfl_xor_sync(0xffffffffu, tm0, 2));
        tm8 = fmaxf(tm8, __shfl_xor_sync(0xffffffffu, tm8, 1));
        tm8 = fmaxf(tm8, __shfl_xor_sync(0xffffffffu, tm8, 2));

        float mn0 = fmaxf(m0, tm0), mn8 = fmaxf(m8, tm8);
        float sc0 = __expf(m0 - mn0), sc8 = __expf(m8 - mn8);
        m0 = mn0; m8 = mn8;

        float rs0 = 0.f, rs8 = 0.f;
#pragma unroll
        for (int j = 0; j < 8; j++) {
            s[j][0] = __expf(s[j][0] - mn0);
            s[j][1] = __expf(s[j][1] - mn0);
            s[j][2] = __expf(s[j][2] - mn8);
            s[j][3] = __expf(s[j][3] - mn8);
            rs0 += s[j][0] + s[j][1];
            rs8 += s[j][2] + s[j][3];
        }
        rs0 += __shfl_xor_sync(0xffffffffu, rs0, 1);
        rs0 += __shfl_xor_sync(0xffffffffu, rs0, 2);
        rs8 += __shfl_xor_sync(0xffffffffu, rs8, 1);
        rs8 += __shfl_xor_sync(0xffffffffu, rs8, 2);
        l0 = l0 * sc0 + rs0;
        l8 = l8 * sc8 + rs8;

#pragma unroll
        for (int j = 0; j < 8; j++) {
            o[j][0] *= sc0; o[j][1] *= sc0;
            o[j][2] *= sc8; o[j][3] *= sc8;
        }

        const int src0 = (lane & ~3) | (c >> 1);
        const bool odd = (c & 1);
#pragma unroll
        for (int kc = 0; kc < 8; kc++) {
            float u0 = __shfl_sync(0xffffffffu, s[kc][0], src0);
            float u1 = __shfl_sync(0xffffffffu, s[kc][1], src0);
            float w0 = __shfl_sync(0xffffffffu, s[kc][0], src0 + 2);
            float w1 = __shfl_sync(0xffffffffu, s[kc][1], src0 + 2);
            float x0 = __shfl_sync(0xffffffffu, s[kc][2], src0);
            float x1 = __shfl_sync(0xffffffffu, s[kc][3], src0);
            float y0 = __shfl_sync(0xffffffffu, s[kc][2], src0 + 2);
            float y1 = __shfl_sync(0xffffffffu, s[kc][3], src0 + 2);
            unsigned a0 = f2tf32(odd ? u1 : u0);
            unsigned a2 = f2tf32(odd ? w1 : w0);
            unsigned a1 = f2tf32(odd ? x1 : x0);
            unsigned a3 = f2tf32(odd ? y1 : y0);
#pragma unroll
            for (int j = 0; j < 8; j++) {
                unsigned b0 = vs[(kc * 8 + c)     * 72 + j * 8 + g];
                unsigned b1 = vs[(kc * 8 + c + 4) * 72 + j * 8 + g];
                mma_tf32(o[j][0], o[j][1], o[j][2], o[j][3], a0, a1, a2, a3, b0, b1);
            }
        }
    }

    float inv0 = 1.0f / l0, inv8 = 1.0f / l8;
#pragma unroll
    for (int j = 0; j < 8; j++) {
        int cc = j * 8 + 2 * c;
        *(float2*)&Ob[(size_t)(q0 + g)     * DDIM + cc] = make_float2(o[j][0] * inv0, o[j][1] * inv0);
        *(float2*)&Ob[(size_t)(q0 + g + 8) * DDIM + cc] = make_float2(o[j][2] * inv8, o[j][3] * inv8);
    }
}

// ---------------- residual + LayerNorm ----------------
__global__ void ln_kernel(const float* __restrict__ hid, const float* __restrict__ inp,
                          const float* __restrict__ gamma, const float* __restrict__ beta,
                          float* __restrict__ out)
{
    size_t row = blockIdx.x;
    int tid = threadIdx.x;
    float x[4];
    float s = 0.f;
#pragma unroll
    for (int t = 0; t < 4; t++) {
        int d = tid + t * 256;
        x[t] = hid[row * DDIM + d] + inp[row * DDIM + d];
        s += x[t];
    }
    __shared__ float sm[8];
    __shared__ float tot;
    for (int o = 16; o > 0; o >>= 1) s += __shfl_xor_sync(0xffffffffu, s, o);
    if ((tid & 31) == 0) sm[tid >> 5] = s;
    __syncthreads();
    if (tid == 0) { float t2 = 0.f; for (int w = 0; w < 8; w++) t2 += sm[w]; tot = t2; }
    __syncthreads();
    float mu = tot * (1.0f / DDIM);
    float vsum = 0.f;
#pragma unroll
    for (int t = 0; t < 4; t++) { float dd = x[t] - mu; vsum += dd * dd; }
    __syncthreads();
    for (int o = 16; o > 0; o >>= 1) vsum += __shfl_xor_sync(0xffffffffu, vsum, o);
    if ((tid & 31) == 0) sm[tid >> 5] = vsum;
    __syncthreads();
    if (tid == 0) { float t2 = 0.f; for (int w = 0; w < 8; w++) t2 += sm[w]; tot = t2; }
    __syncthreads();
    float var = tot * (1.0f / DDIM);
    float inv = 1.0f / sqrtf(var + 1e-12f);
#pragma unroll
    for (int t = 0; t < 4; t++) {
        int d = tid + t * 256;
        out[row * DDIM + d] = (x[t] - mu) * inv * gamma[d] + beta[d];
    }
}

// ---------------- driver ----------------
extern "C" void kernel_launch(void* const* d_in, const int* in_sizes, int n_in,
                              void* d_out, int out_size)
{
    const float* X   = (const float*)d_in[0];
    const float* Wq  = (const float*)d_in[1];
    const float* bq  = (const float*)d_in[2];
    const float* Wk  = (const float*)d_in[3];
    const float* bk  = (const float*)d_in[4];
    const float* Wv  = (const float*)d_in[5];
    const float* bv  = (const float*)d_in[6];
    const float* Wd  = (const float*)d_in[7];
    const float* bd  = (const float*)d_in[8];
    const float* gamma     = (const float*)d_in[9];
    const float* beta      = (const float*)d_in[10];
    const float* delta     = (const float*)d_in[11];
    const float* b_euler   = (const float*)d_in[12];
    const float* log_scale = (const float*)d_in[13];
    float* out = (float*)d_out;

    float *q, *k, *v, *q2, *k2, *ctx, *hid, *Pq, *Pk, *scq, *sck, *pX, *meanX, *bsq, *bsk;
    { void* p;
      cudaGetSymbolAddress(&p, g_q);     q     = (float*)p;
      cudaGetSymbolAddress(&p, g_k);     k     = (float*)p;
      cudaGetSymbolAddress(&p, g_v);     v     = (float*)p;
      cudaGetSymbolAddress(&p, g_q2);    q2    = (float*)p;
      cudaGetSymbolAddress(&p, g_k2);    k2    = (float*)p;
      cudaGetSymbolAddress(&p, g_ctx);   ctx   = (float*)p;
      cudaGetSymbolAddress(&p, g_hid);   hid   = (float*)p;
      cudaGetSymbolAddress(&p, g_Pq);    Pq    = (float*)p;
      cudaGetSymbolAddress(&p, g_Pk);    Pk    = (float*)p;
      cudaGetSymbolAddress(&p, g_scq);   scq   = (float*)p;
      cudaGetSymbolAddress(&p, g_sck);   sck   = (float*)p;
      cudaGetSymbolAddress(&p, g_partX); pX    = (float*)p;
      cudaGetSymbolAddress(&p, g_meanX); meanX = (float*)p;
      cudaGetSymbolAddress(&p, g_bsq);   bsq   = (float*)p;
      cudaGetSymbolAddress(&p, g_bsk);   bsk   = (float*)p;
    }

    const int M = BB * LLEN;   // 4096
    const long long sQ = (long long)LLEN * DDIM;
    const long long sP = (long long)DDIM * DDIM;

    // exact scores path (fp32)
    colmean_part<<<dim3(BB, 16), 1024>>>(X, pX);
    colmean_fin<<<BB, 1024>>>(pX, meanX);
    score_kernel<<<dim3(DDIM / 8, BB, 2), 256>>>(meanX, Wq, bq, Wk, bk, scq, sck);

    // projections (bf16 tensor core, ldmatrix)
    gemm_bf16<<<dim3(DDIM/128, M/128, 1), 256>>>(X, Wq, bq, q, M, DDIM, DDIM, 0, 0, 0, 0, nullptr, nullptr, nullptr);
    gemm_bf16<<<dim3(DDIM/128, M/128, 1), 256>>>(X, Wk, bk, k, M, DDIM, DDIM, 0, 0, 0, 0, nullptr, nullptr, nullptr);
    gemm_bf16<<<dim3(DDIM/128, M/128, 1), 256>>>(X, Wv, bv, v, M, DDIM, DDIM, 0, 0, 0, 0, nullptr, nullptr, nullptr);

    // neural sort permutation matrices (fp32-exact scores)
    bsum_kernel<<<dim3(BB, 2), 1024>>>(scq, sck, bsq, bsk);
    sortP_kernel<<<dim3(DDIM, BB, 2), 256>>>(scq, bsq, sck, bsk, Pq, Pk);

    // v_sorted = x @ P^T  with fused Euler epilogue (mode 1 = +b_euler for q, 2 = k)
    gemm_bf16<<<dim3(DDIM/128, LLEN/128, BB), 256>>>(q, Pq, nullptr, q2, LLEN, DDIM, DDIM,
                                                     sQ, sP, sQ, 1, delta, b_euler, log_scale);
    gemm_bf16<<<dim3(DDIM/128, LLEN/128, BB), 256>>>(k, Pk, nullptr, k2, LLEN, DDIM, DDIM,
                                                     sQ, sP, sQ, 2, delta, b_euler, log_scale);

    // attention (tf32 tensor core flash)
    flash_tf32<<<dim3(LLEN/128, BB*NHEAD), 256>>>(q2, k2, v, ctx);

    // output projection (bf16)
    gemm_bf16<<<dim3(DDIM/128, M/128, 1), 256>>>(ctx, Wd, bd, hid, M, DDIM, DDIM, 0, 0, 0, 0, nullptr, nullptr, nullptr);

    // residual + layernorm
    ln_kernel<<<M, 256>>>(hid, X, gamma, beta, out);
}